// round 9
// baseline (speedup 1.0000x reference)
#include <cuda_runtime.h>
#include <cstddef>
#include <cstdint>

#define HH 320
#define WW 320
#define CC 64
#define BB 2
#define HW (HH*WW)              // 102400
#define CHW ((size_t)CC*HW)     // 6553600
#define TENSOR_ELEMS (BB*CHW)   // 13107200

#define QT 16                   // attention q-tile

// Scratch (static device arrays; no allocation allowed)
__device__ uint32_t g_Mt[2*CC*CC];           // tf32(M^T * log2e) per dir
__device__ uint32_t g_buf[2][TENSOR_ELEMS];  // buffer_d, buffer_u (tf32 bits)
__device__ uint32_t g_t[2][TENSOR_ELEMS];    // relu(conv1) intermediates (tf32 bits)
__device__ uint32_t g_utf[TENSOR_ELEMS];     // tf32(u)
__device__ uint32_t g_dtf[TENSOR_ELEMS];     // tf32(d)
// pre-permuted tf32 weights: [chunk][tap][o][18]
__device__ uint32_t g_wp1a[8*9*64*18];
__device__ uint32_t g_wp2a[8*9*64*18];
__device__ uint32_t g_wp1b[4*9*64*18];
__device__ uint32_t g_wp2b[4*9*64*18];

__device__ __forceinline__ uint32_t f2tf32(float f) {
    uint32_t r; asm("cvt.rna.tf32.f32 %0, %1;" : "=r"(r) : "f"(f)); return r;
}
__device__ __forceinline__ void mma_tf32(float4& d,
        uint32_t a0, uint32_t a1, uint32_t a2, uint32_t a3,
        uint32_t b0, uint32_t b1) {
    asm("mma.sync.aligned.m16n8k8.row.col.f32.tf32.tf32.f32 "
        "{%0,%1,%2,%3}, {%4,%5,%6,%7}, {%8,%9}, {%0,%1,%2,%3};"
        : "+f"(d.x), "+f"(d.y), "+f"(d.z), "+f"(d.w)
        : "r"(a0), "r"(a1), "r"(a2), "r"(a3), "r"(b0), "r"(b1));
}
__device__ __forceinline__ void cp16(uint32_t saddr, const void* gaddr, uint32_t sz) {
    asm volatile("cp.async.cg.shared.global [%0], [%1], 16, %2;"
                 :: "r"(saddr), "l"(gaddr), "r"(sz));
}
__device__ __forceinline__ uint32_t fu(float f) { return __float_as_uint(f); }

#define BAR_ARRIVE(id)  asm volatile("bar.arrive %0, 256;" :: "r"(id))
#define BAR_SYNC256(id) asm volatile("bar.sync %0, 256;" :: "r"(id) : "memory")
#define BAR_SYNC128(id) asm volatile("bar.sync %0, 128;" :: "r"(id) : "memory")

// ---------------------------------------------------------------------------
// prep: convert u,d to tf32 bit arrays
// ---------------------------------------------------------------------------
__global__ void kprepin(const float* __restrict__ u, const float* __restrict__ d) {
    for (size_t i = (size_t)blockIdx.x*256 + threadIdx.x; i < TENSOR_ELEMS;
         i += (size_t)gridDim.x*256) {
        g_utf[i] = f2tf32(u[i]);
        g_dtf[i] = f2tf32(d[i]);
    }
}

// ---------------------------------------------------------------------------
// prep: all 4 conv weights in ONE launch (keeps kconv at launch #5 for ncu)
// ---------------------------------------------------------------------------
__device__ __forceinline__ void prepw_one(const float* __restrict__ W,
                                          uint32_t* __restrict__ dst,
                                          int cin, int i) {
    int w    = i % 18;
    int rest = i / 18;
    int o    = rest % 64;
    int rest2= rest / 64;
    int t    = rest2 % 9;
    int chunk= rest2 / 9;
    uint32_t v = 0;
    if (w < 16) {
        int s = w >> 3, p = w & 7;
        int c = (p >> 1) + ((p & 1) << 2);
        int cinidx = chunk*16 + s*8 + c;
        v = f2tf32(W[(size_t)o*(cin*9) + (size_t)cinidx*9 + t]);
    }
    dst[i] = v;
}

#define WPA (8*9*64*18)   // 82944
#define WPB (4*9*64*18)   // 41472

__global__ void kprepwAll(const float* __restrict__ W1a, const float* __restrict__ W2a,
                          const float* __restrict__ W1b, const float* __restrict__ W2b) {
    int total = 2*WPA + 2*WPB;
    for (int i = blockIdx.x*256 + threadIdx.x; i < total; i += gridDim.x*256) {
        if (i < WPA)                 prepw_one(W1a, g_wp1a, 128, i);
        else if (i < 2*WPA)          prepw_one(W2a, g_wp2a, 128, i - WPA);
        else if (i < 2*WPA + WPB)    prepw_one(W1b, g_wp1b, 64,  i - 2*WPA);
        else                         prepw_one(W2b, g_wp2b, 64,  i - 2*WPA - WPB);
    }
}

// ---------------------------------------------------------------------------
// Kernel 1: Mt[dir][b][a] = tf32( log2e * sum_c Wq[c][a] * Wk[c][b] )
// both dirs in one launch (blockIdx.x = dir)
// ---------------------------------------------------------------------------
__global__ void kcomputeM2(const float* __restrict__ Wu1, const float* __restrict__ Wd2,
                           const float* __restrict__ Wd1, const float* __restrict__ Wu2) {
    __shared__ float sq[64*64];
    __shared__ float sk[64*64];
    int dir = blockIdx.x;
    const float* Wq = dir ? Wd1 : Wu1;
    const float* Wk = dir ? Wu2 : Wd2;
    int t = threadIdx.x;
    for (int i = t; i < 4096; i += 256) { sq[i] = Wq[i]; sk[i] = Wk[i]; }
    __syncthreads();
    const float LOG2E = 1.4426950408889634f;
    for (int i = t; i < 4096; i += 256) {
        int a = i >> 6, b = i & 63;
        float s = 0.f;
        #pragma unroll 16
        for (int c = 0; c < 64; c++) s += sq[c*64 + a] * sk[c*64 + b];
        g_Mt[dir*4096 + b*64 + a] = f2tf32(s * LOG2E);
    }
}

// ---------------------------------------------------------------------------
// Kernel 2: warp-specialized pipelined axial attention.
// Warps 0-3: MMA (R, score, attend). Warps 4-7: softmax (EX2).
// smem: su[64][328], sd[64][328], sP[2][QT][328], sR[64][24]
// ---------------------------------------------------------------------------
#define ATTN_SMEM ((64*328*2 + 2*QT*328 + 64*24)*4)   // 216064 B

__global__ __launch_bounds__(256)
void kattn(int dummy) {
    extern __shared__ float smem[];
    float* su = smem;                  // 64*328
    float* sd = su + 64*328;
    float* sP = sd + 64*328;           // 2 * QT*328
    float* sR = sP + 2*QT*328;         // 64*24

    int tid  = threadIdx.x;
    int lane = tid & 31, warp = tid >> 5;
    int gid  = lane >> 2, tid4 = lane & 3;
    int b = blockIdx.x / HH, h = blockIdx.x % HH;
    const uint32_t* ub = g_utf + (size_t)b*CHW + (size_t)h*WW;
    const uint32_t* db = g_dtf + (size_t)b*CHW + (size_t)h*WW;

    for (int i = tid; i < 64*80; i += 256) {
        int c = i / 80, q4 = (i % 80) * 4;
        uint4 vu = *(const uint4*)(ub + (size_t)c*HW + q4);
        uint4 vd = *(const uint4*)(db + (size_t)c*HW + q4);
        *(uint4*)&su[c*328 + q4] = vu;
        *(uint4*)&sd[c*328 + q4] = vd;
    }
    __syncthreads();

    bool isMMA = warp < 4;
    int w = warp & 3;

    for (int dir = 0; dir < 2; dir++) {
        const float* sQ = dir ? sd : su;
        const float* sV = dir ? su : sd;
        uint32_t* outg = g_buf[dir] + (size_t)b*CHW + (size_t)h*WW;

        if (isMMA) {
            // Mt fragments: rows r = w*16+gid(+8)
            const uint32_t* Mt = g_Mt + dir*4096;
            uint32_t am[8][4];
            {
                int r = w*16 + gid;
                #pragma unroll
                for (int k = 0; k < 8; k++) {
                    int c0 = k*8 + tid4;
                    am[k][0] = Mt[r*64 + c0];
                    am[k][1] = Mt[(r+8)*64 + c0];
                    am[k][2] = Mt[r*64 + c0 + 4];
                    am[k][3] = Mt[(r+8)*64 + c0 + 4];
                }
            }

            for (int t = 0; t <= 20; t++) {
                if (t < 20) {
                    int q0 = t*QT;
                    // ---- R[b][q] (m=b 16 rows this warp, n=q 16) ----
                    float4 rc[2];
                    rc[0] = make_float4(0.f,0.f,0.f,0.f);
                    rc[1] = make_float4(0.f,0.f,0.f,0.f);
                    #pragma unroll
                    for (int k = 0; k < 8; k++) {
                        #pragma unroll
                        for (int nt = 0; nt < 2; nt++) {
                            int qq = q0 + nt*8 + gid;
                            uint32_t b0 = fu(sQ[(k*8 + tid4)*328 + qq]);
                            uint32_t b1 = fu(sQ[(k*8 + tid4 + 4)*328 + qq]);
                            mma_tf32(rc[nt], am[k][0], am[k][1], am[k][2], am[k][3], b0, b1);
                        }
                    }
                    #pragma unroll
                    for (int nt = 0; nt < 2; nt++) {
                        int q = nt*8 + 2*tid4;
                        int bb = w*16 + gid;
                        *(uint2*)&sR[bb*24 + q]     = make_uint2(f2tf32(rc[nt].x), f2tf32(rc[nt].y));
                        *(uint2*)&sR[(bb+8)*24 + q] = make_uint2(f2tf32(rc[nt].z), f2tf32(rc[nt].w));
                    }
                    BAR_SYNC128(5);   // MMA-group: R complete

                    // ---- S[q][v] (m=q 16, n=v 80 this warp, k=b 64) ----
                    float* Pb = sP + (t & 1)*QT*328;
                    float4 sc[10];
                    #pragma unroll
                    for (int nt = 0; nt < 10; nt++) sc[nt] = make_float4(0.f,0.f,0.f,0.f);
                    #pragma unroll
                    for (int kk = 0; kk < 8; kk++) {
                        uint32_t a0 = fu(sR[(kk*8 + tid4)*24 + gid]);
                        uint32_t a1 = fu(sR[(kk*8 + tid4)*24 + gid + 8]);
                        uint32_t a2 = fu(sR[(kk*8 + tid4 + 4)*24 + gid]);
                        uint32_t a3 = fu(sR[(kk*8 + tid4 + 4)*24 + gid + 8]);
                        #pragma unroll
                        for (int nt = 0; nt < 10; nt++) {
                            int vv = w*80 + nt*8 + gid;
                            uint32_t b0 = fu(sV[(kk*8 + tid4)*328 + vv]);
                            uint32_t b1 = fu(sV[(kk*8 + tid4 + 4)*328 + vv]);
                            mma_tf32(sc[nt], a0, a1, a2, a3, b0, b1);
                        }
                    }
                    #pragma unroll
                    for (int nt = 0; nt < 10; nt++) {
                        int v = w*80 + nt*8 + 2*tid4;
                        *(float2*)&Pb[gid*328 + v]     = make_float2(sc[nt].x, sc[nt].y);
                        *(float2*)&Pb[(gid+8)*328 + v] = make_float2(sc[nt].z, sc[nt].w);
                    }
                    __threadfence_block();
                    BAR_ARRIVE(1 + (t & 1));   // S(t) ready
                }
                if (t > 0) {
                    int tp = t - 1;
                    BAR_SYNC256(3 + (tp & 1)); // wait P(tp)
                    float* Pb = sP + (tp & 1)*QT*328;
                    // ---- out[c][q] (m=c 16 this warp, n=q 16, k=v 320) ----
                    float4 oc[2];
                    oc[0] = make_float4(0.f,0.f,0.f,0.f);
                    oc[1] = make_float4(0.f,0.f,0.f,0.f);
                    #pragma unroll 4
                    for (int k = 0; k < 40; k++) {
                        int kb = k*8;
                        uint32_t a0 = fu(sV[(w*16 + gid)*328 + kb + tid4]);
                        uint32_t a1 = fu(sV[(w*16 + gid + 8)*328 + kb + tid4]);
                        uint32_t a2 = fu(sV[(w*16 + gid)*328 + kb + tid4 + 4]);
                        uint32_t a3 = fu(sV[(w*16 + gid + 8)*328 + kb + tid4 + 4]);
                        #pragma unroll
                        for (int nt = 0; nt < 2; nt++) {
                            uint32_t b0 = fu(Pb[(nt*8 + gid)*328 + kb + tid4]);
                            uint32_t b1 = fu(Pb[(nt*8 + gid)*328 + kb + tid4 + 4]);
                            mma_tf32(oc[nt], a0, a1, a2, a3, b0, b1);
                        }
                    }
                    #pragma unroll
                    for (int nt = 0; nt < 2; nt++) {
                        int c = w*16 + gid;
                        int q = tp*QT + nt*8 + 2*tid4;
                        uint2 w0 = make_uint2(f2tf32(oc[nt].x), f2tf32(oc[nt].y));
                        uint2 w1 = make_uint2(f2tf32(oc[nt].z), f2tf32(oc[nt].w));
                        *(uint2*)(outg + (size_t)c*HW + q)     = w0;
                        *(uint2*)(outg + (size_t)(c+8)*HW + q) = w1;
                    }
                }
            }
        } else {
            // ---- softmax warps: 4 rows each per tile ----
            int sw = warp - 4;
            for (int t = 0; t < 20; t++) {
                BAR_SYNC256(1 + (t & 1));   // wait S(t)
                float* Pb = sP + (t & 1)*QT*328;
                #pragma unroll
                for (int i = 0; i < 4; i++) {
                    int row = sw*4 + i;
                    float a[10];
                    #pragma unroll
                    for (int j = 0; j < 10; j++) a[j] = Pb[row*328 + lane + 32*j];
                    float m = a[0];
                    #pragma unroll
                    for (int j = 1; j < 10; j++) m = fmaxf(m, a[j]);
                    #pragma unroll
                    for (int o = 16; o > 0; o >>= 1) m = fmaxf(m, __shfl_xor_sync(~0u, m, o));
                    float s = 0.f;
                    #pragma unroll
                    for (int j = 0; j < 10; j++) { a[j] = exp2f(a[j] - m); s += a[j]; }
                    #pragma unroll
                    for (int o = 16; o > 0; o >>= 1) s += __shfl_xor_sync(~0u, s, o);
                    float inv = 1.f / s;
                    #pragma unroll
                    for (int j = 0; j < 10; j++)
                        Pb[row*328 + lane + 32*j] = __uint_as_float(f2tf32(a[j]*inv));
                }
                __threadfence_block();
                BAR_ARRIVE(3 + (t & 1));    // P(t) ready
            }
        }
        __syncthreads();
    }
}

// ---------------------------------------------------------------------------
// Kernel 3: tf32 implicit-GEMM 3x3 conv (R6 version, unchanged).
// ---------------------------------------------------------------------------
#define PLANE 728
#define SIN_U32 (16*PLANE)              // 11648
#define SW_U32  (9*64*18)               // 10368
#define STAGE_U32 (SIN_U32 + SW_U32)    // 22016
#define CONV_SMEM (STAGE_U32*2*4)       // 176128 bytes

template<int CIN, bool FUSE>
__global__ __launch_bounds__(512, 1)
void kconv(const uint32_t* __restrict__ in1u, const uint32_t* __restrict__ in1d,
           const uint32_t* __restrict__ in2u, const uint32_t* __restrict__ in2d,
           const uint32_t* __restrict__ wpu,  const uint32_t* __restrict__ wpd,
           void* __restrict__ outu, void* __restrict__ outd) {
    extern __shared__ uint32_t csm[];

    int tid  = threadIdx.x;
    int lane = tid & 31, warp = tid >> 5;
    int x0 = blockIdx.x * 64;
    int y0 = blockIdx.y * 8;
    int z  = blockIdx.z;
    int b  = z & 1, st = z >> 1;
    size_t bCHW = (size_t)b*CHW;

    const uint32_t* in1 = st ? in1d : in1u;
    const uint32_t* in2 = st ? in2d : in2u;
    const uint32_t* wp  = st ? wpd  : wpu;
    void* outv          = st ? outd : outu;

    int warp_o = warp & 1;
    int warp_y = warp >> 1;
    int lq = lane >> 2;
    int lr = lane & 3;

    uint32_t s_base = (uint32_t)__cvta_generic_to_shared(csm);
    const int NCH = CIN/16;

    auto stage = [&](int cb, int bufi) {
        uint32_t sb = s_base + bufi*STAGE_U32*4;
        for (int i = tid; i < 2880; i += 512) {
            int c   = i / 180;
            int rem = i % 180;
            int r   = rem / 18;
            int q   = rem % 18;
            int gy = y0 + r - 1;
            int gx = x0 - 4 + q*4;
            uint32_t ok = (gy >= 0 && gy < HH && gx >= 0 && gx < WW) ? 16u : 0u;
            int cg = cb*16 + c;
            const uint32_t* plane;
            if (CIN == 128 && cg >= 64) plane = in2 + bCHW + (size_t)(cg - 64)*HW;
            else                        plane = in1 + bCHW + (size_t)cg*HW;
            const uint32_t* gsrc = ok ? (plane + gy*WW + gx) : plane;
            cp16(sb + (c*PLANE + r*72 + q*4)*4, gsrc, ok);
        }
        const uint32_t* wsrc = wp + cb*SW_U32;
        for (int i = tid; i < SW_U32/4; i += 512)
            cp16(sb + (SIN_U32 + i*4)*4, wsrc + i*4, 16);
    };

    float4 acc[2][8];
    #pragma unroll
    for (int mt = 0; mt < 2; mt++)
        #pragma unroll
        for (int nt = 0; nt < 8; nt++) acc[mt][nt] = make_float4(0.f,0.f,0.f,0.f);

    stage(0, 0);
    asm volatile("cp.async.commit_group;" ::: "memory");

    for (int cb = 0; cb < NCH; cb++) {
        if (cb + 1 < NCH) {
            stage(cb + 1, (cb + 1) & 1);
            asm volatile("cp.async.commit_group;" ::: "memory");
            asm volatile("cp.async.wait_group 1;" ::: "memory");
        } else {
            asm volatile("cp.async.wait_group 0;" ::: "memory");
        }
        __syncthreads();

        const uint32_t* sin_ = csm + (cb & 1)*STAGE_U32;
        const uint32_t* sw_  = sin_ + SIN_U32;

        #pragma unroll
        for (int t = 0; t < 9; t++) {
            int ky = t/3, kx = t - ky*3;
            int row = warp_y + ky;
            int bbase = row*72 + kx + 3 + lq;
            #pragma unroll
            for (int s = 0; s < 2; s++) {
                int aoff = (t*64 + warp_o*32)*18 + s*8 + 2*lr;
                uint2 a00 = *(const uint2*)&sw_[aoff + lq*18];
                uint2 a01 = *(const uint2*)&sw_[aoff + (lq+8)*18];
                uint2 a10 = *(const uint2*)&sw_[aoff + (lq+16)*18];
                uint2 a11 = *(const uint2*)&sw_[aoff + (lq+24)*18];
                int p0 = (s*8 + lr)*PLANE + bbase;
                int p1 = p0 + 4*PLANE;
                #pragma unroll
                for (int nt = 0; nt < 8; nt++) {
                    uint32_t b0 = sin_[p0 + 8*nt];
                    uint32_t b1 = sin_[p1 + 8*nt];
                    mma_tf32(acc[0][nt], a00.x, a01.x, a00.y, a01.y, b0, b1);
                    mma_tf32(acc[1][nt], a10.x, a11.x, a10.y, a11.y, b0, b1);
                }
            }
        }
        __syncthreads();
    }

    int y = y0 + warp_y;
    #pragma unroll
    for (int mt = 0; mt < 2; mt++) {
        int o_lo = warp_o*32 + mt*16 + lq;
        #pragma unroll
        for (int nt = 0; nt < 8; nt++) {
            int x = x0 + nt*8 + 2*lr;
            float4 v = acc[mt][nt];
            size_t off = bCHW + (size_t)o_lo*HW + (size_t)y*WW + x;
            if (FUSE) {
                uint32_t* outp = (uint32_t*)outv;
                uint2 r0 = make_uint2(f2tf32(fmaxf(v.x, 0.f)), f2tf32(fmaxf(v.y, 0.f)));
                uint2 r1 = make_uint2(f2tf32(fmaxf(v.z, 0.f)), f2tf32(fmaxf(v.w, 0.f)));
                *(uint2*)(outp + off)            = r0;
                *(uint2*)(outp + off + 8*HW)     = r1;
            } else {
                float* outp = (float*)outv;
                *(float2*)(outp + off)           = make_float2(v.x, v.y);
                *(float2*)(outp + off + 8*HW)    = make_float2(v.z, v.w);
            }
        }
    }
}

// ---------------------------------------------------------------------------
extern "C" void kernel_launch(void* const* d_in, const int* in_sizes, int n_in,
                              void* d_out, int out_size) {
    const float* u   = (const float*)d_in[0];
    const float* d   = (const float*)d_in[1];
    const float* Wu1 = (const float*)d_in[2];
    const float* Wu2 = (const float*)d_in[3];
    const float* Wd1 = (const float*)d_in[4];
    const float* Wd2 = (const float*)d_in[5];
    const float* W1a = (const float*)d_in[6];
    const float* W1b = (const float*)d_in[7];
    const float* W2a = (const float*)d_in[8];
    const float* W2b = (const float*)d_in[9];
    float* out = (float*)d_out;

    cudaFuncSetAttribute(kattn, cudaFuncAttributeMaxDynamicSharedMemorySize, ATTN_SMEM);
    cudaFuncSetAttribute(kconv<128, true>,  cudaFuncAttributeMaxDynamicSharedMemorySize, CONV_SMEM);
    cudaFuncSetAttribute(kconv<64, false>,  cudaFuncAttributeMaxDynamicSharedMemorySize, CONV_SMEM);

    uint32_t *pbuf0, *pbuf1, *pt0, *pt1, *putf, *pdtf;
    uint32_t *pw1a, *pw2a, *pw1b, *pw2b;
    cudaGetSymbolAddress((void**)&pbuf0, g_buf);   pbuf1 = pbuf0 + TENSOR_ELEMS;
    cudaGetSymbolAddress((void**)&pt0,   g_t);     pt1   = pt0   + TENSOR_ELEMS;
    cudaGetSymbolAddress((void**)&putf,  g_utf);
    cudaGetSymbolAddress((void**)&pdtf,  g_dtf);
    cudaGetSymbolAddress((void**)&pw1a,  g_wp1a);
    cudaGetSymbolAddress((void**)&pw2a,  g_wp2a);
    cudaGetSymbolAddress((void**)&pw1b,  g_wp1b);
    cudaGetSymbolAddress((void**)&pw2b,  g_wp2b);

    // launch #1..#4: prep + attention
    kprepin<<<2048, 256>>>(u, d);
    kprepwAll<<<972, 256>>>(W1a, W2a, W1b, W2b);
    kcomputeM2<<<2, 256>>>(Wu1, Wd2, Wd1, Wu2);
    kattn<<<BB*HH, 256, ATTN_SMEM>>>(0);

    // launch #5 (ncu-profiled): conv1; launch #6: conv2
    dim3 grid(WW/64, HH/8, 4);
    kconv<128, true><<<grid, 512, CONV_SMEM>>>(putf, pdtf, pbuf0, pbuf1,
                                               pw1a, pw2a, pt0, pt1);
    kconv<64, false><<<grid, 512, CONV_SMEM>>>(pt0, pt1, pt0, pt1,
                                               pw1b, pw2b, out, out + TENSOR_ELEMS);
}

// round 10
// speedup vs baseline: 1.0503x; 1.0503x over previous
#include <cuda_runtime.h>
#include <cstddef>
#include <cstdint>

#define HH 320
#define WW 320
#define CC 64
#define BB 2
#define HW (HH*WW)              // 102400
#define CHW ((size_t)CC*HW)     // 6553600
#define TENSOR_ELEMS (BB*CHW)   // 13107200

// Scratch (static device arrays; no allocation allowed)
__device__ uint32_t g_Mt[2*CC*CC];           // tf32(M^T * log2e) per dir
__device__ uint32_t g_buf[2][TENSOR_ELEMS];  // buffer_d, buffer_u (tf32 bits)
__device__ uint32_t g_t[2][TENSOR_ELEMS];    // relu(conv1) intermediates (tf32 bits)
__device__ uint32_t g_utf[TENSOR_ELEMS];     // tf32(u)
__device__ uint32_t g_dtf[TENSOR_ELEMS];     // tf32(d)
// pre-permuted tf32 weights: [chunk][tap][o][18]
__device__ uint32_t g_wp1a[8*9*64*18];
__device__ uint32_t g_wp2a[8*9*64*18];
__device__ uint32_t g_wp1b[4*9*64*18];
__device__ uint32_t g_wp2b[4*9*64*18];

__device__ __forceinline__ uint32_t f2tf32(float f) {
    uint32_t r; asm("cvt.rna.tf32.f32 %0, %1;" : "=r"(r) : "f"(f)); return r;
}
__device__ __forceinline__ void mma_tf32(float4& d,
        uint32_t a0, uint32_t a1, uint32_t a2, uint32_t a3,
        uint32_t b0, uint32_t b1) {
    asm("mma.sync.aligned.m16n8k8.row.col.f32.tf32.tf32.f32 "
        "{%0,%1,%2,%3}, {%4,%5,%6,%7}, {%8,%9}, {%0,%1,%2,%3};"
        : "+f"(d.x), "+f"(d.y), "+f"(d.z), "+f"(d.w)
        : "r"(a0), "r"(a1), "r"(a2), "r"(a3), "r"(b0), "r"(b1));
}
__device__ __forceinline__ void cp16(uint32_t saddr, const void* gaddr, uint32_t sz) {
    asm volatile("cp.async.cg.shared.global [%0], [%1], 16, %2;"
                 :: "r"(saddr), "l"(gaddr), "r"(sz));
}
__device__ __forceinline__ uint32_t fu(float f) { return __float_as_uint(f); }

// ---------------------------------------------------------------------------
// prep: convert u,d to tf32 bit arrays
// ---------------------------------------------------------------------------
__global__ void kprepin(const float* __restrict__ u, const float* __restrict__ d) {
    for (size_t i = (size_t)blockIdx.x*256 + threadIdx.x; i < TENSOR_ELEMS;
         i += (size_t)gridDim.x*256) {
        g_utf[i] = f2tf32(u[i]);
        g_dtf[i] = f2tf32(d[i]);
    }
}

// ---------------------------------------------------------------------------
// prep: all 4 conv weights in ONE launch
// ---------------------------------------------------------------------------
__device__ __forceinline__ void prepw_one(const float* __restrict__ W,
                                          uint32_t* __restrict__ dst,
                                          int cin, int i) {
    int w    = i % 18;
    int rest = i / 18;
    int o    = rest % 64;
    int rest2= rest / 64;
    int t    = rest2 % 9;
    int chunk= rest2 / 9;
    uint32_t v = 0;
    if (w < 16) {
        int s = w >> 3, p = w & 7;
        int c = (p >> 1) + ((p & 1) << 2);
        int cinidx = chunk*16 + s*8 + c;
        v = f2tf32(W[(size_t)o*(cin*9) + (size_t)cinidx*9 + t]);
    }
    dst[i] = v;
}

#define WPA (8*9*64*18)   // 82944
#define WPB (4*9*64*18)   // 41472

__global__ void kprepwAll(const float* __restrict__ W1a, const float* __restrict__ W2a,
                          const float* __restrict__ W1b, const float* __restrict__ W2b) {
    int total = 2*WPA + 2*WPB;
    for (int i = blockIdx.x*256 + threadIdx.x; i < total; i += gridDim.x*256) {
        if (i < WPA)                 prepw_one(W1a, g_wp1a, 128, i);
        else if (i < 2*WPA)          prepw_one(W2a, g_wp2a, 128, i - WPA);
        else if (i < 2*WPA + WPB)    prepw_one(W1b, g_wp1b, 64,  i - 2*WPA);
        else                         prepw_one(W2b, g_wp2b, 64,  i - 2*WPA - WPB);
    }
}

// ---------------------------------------------------------------------------
// Kernel 1: Mt[dir][b][a] = tf32( log2e * sum_c Wq[c][a] * Wk[c][b] )
// ---------------------------------------------------------------------------
__global__ void kcomputeM2(const float* __restrict__ Wu1, const float* __restrict__ Wd2,
                           const float* __restrict__ Wd1, const float* __restrict__ Wu2) {
    __shared__ float sq[64*64];
    __shared__ float sk[64*64];
    int dir = blockIdx.x;
    const float* Wq = dir ? Wd1 : Wu1;
    const float* Wk = dir ? Wu2 : Wd2;
    int t = threadIdx.x;
    for (int i = t; i < 4096; i += 256) { sq[i] = Wq[i]; sk[i] = Wk[i]; }
    __syncthreads();
    const float LOG2E = 1.4426950408889634f;
    for (int i = t; i < 4096; i += 256) {
        int a = i >> 6, b = i & 63;
        float s = 0.f;
        #pragma unroll 16
        for (int c = 0; c < 64; c++) s += sq[c*64 + a] * sk[c*64 + b];
        g_Mt[dir*4096 + b*64 + a] = f2tf32(s * LOG2E);
    }
}

// ---------------------------------------------------------------------------
// Kernel 2: tensor-core axial attention, 16 warps (512 thr), all-warp phases.
// smem: su[64][328], sd[64][328], sP[32][328], sR[64][36]  (219136 B)
// ---------------------------------------------------------------------------
#define ATTN_SMEM ((64*328*2 + 32*328 + 64*36)*4)

__global__ __launch_bounds__(512)
void kattn(int dummy) {
    extern __shared__ float smem[];
    float* su = smem;                 // 64*328
    float* sd = su + 64*328;
    float* sP = sd + 64*328;          // 32*328
    float* sR = sP + 32*328;          // 64*36

    int tid  = threadIdx.x;
    int lane = tid & 31, warp = tid >> 5;    // 16 warps
    int gid  = lane >> 2, tid4 = lane & 3;
    int b = blockIdx.x / HH, h = blockIdx.x % HH;
    const uint32_t* ub = g_utf + (size_t)b*CHW + (size_t)h*WW;
    const uint32_t* db = g_dtf + (size_t)b*CHW + (size_t)h*WW;

    for (int i = tid; i < 64*80; i += 512) {
        int c = i / 80, q4 = (i % 80) * 4;
        uint4 vu = *(const uint4*)(ub + (size_t)c*HW + q4);
        uint4 vd = *(const uint4*)(db + (size_t)c*HW + q4);
        *(uint4*)&su[c*328 + q4] = vu;
        *(uint4*)&sd[c*328 + q4] = vd;
    }

    for (int dir = 0; dir < 2; dir++) {
        const float* sQ = dir ? sd : su;
        const float* sV = dir ? su : sd;
        uint32_t* outg = g_buf[dir] + (size_t)b*CHW + (size_t)h*WW;

        // Mt fragments for R GEMM: warp -> (bg = warp&3 [16 b-rows], rq = warp>>2 [8 q])
        const uint32_t* Mt = g_Mt + dir*4096;
        int bg = warp & 3, rq = warp >> 2;
        uint32_t am[8][4];
        {
            int r = bg*16 + gid;
            #pragma unroll
            for (int k = 0; k < 8; k++) {
                int c0 = k*8 + tid4;
                am[k][0] = Mt[r*64 + c0];
                am[k][1] = Mt[(r+8)*64 + c0];
                am[k][2] = Mt[r*64 + c0 + 4];
                am[k][3] = Mt[(r+8)*64 + c0 + 4];
            }
        }

        for (int q0 = 0; q0 < WW; q0 += 32) {
            __syncthreads();    // sR, sP free from previous tile

            // ---- R[b][q]: warp = 16b x 8q ----
            float4 rc = make_float4(0.f,0.f,0.f,0.f);
            #pragma unroll
            for (int k = 0; k < 8; k++) {
                int qq = q0 + rq*8 + gid;
                uint32_t b0 = fu(sQ[(k*8 + tid4)*328 + qq]);
                uint32_t b1 = fu(sQ[(k*8 + tid4 + 4)*328 + qq]);
                mma_tf32(rc, am[k][0], am[k][1], am[k][2], am[k][3], b0, b1);
            }
            {
                int q = rq*8 + 2*tid4;
                int bb = bg*16 + gid;
                *(uint2*)&sR[bb*36 + q]     = make_uint2(f2tf32(rc.x), f2tf32(rc.y));
                *(uint2*)&sR[(bb+8)*36 + q] = make_uint2(f2tf32(rc.z), f2tf32(rc.w));
            }
            __syncthreads();

            // ---- S[q][v]: warp = 16q x 40v (qg = warp>>3, vg = warp&7) ----
            {
                int qg = warp >> 3, vg = warp & 7;
                float4 sc[5];
                #pragma unroll
                for (int nt = 0; nt < 5; nt++) sc[nt] = make_float4(0.f,0.f,0.f,0.f);
                #pragma unroll
                for (int kk = 0; kk < 8; kk++) {
                    uint32_t a0 = fu(sR[(kk*8 + tid4)*36 + qg*16 + gid]);
                    uint32_t a1 = fu(sR[(kk*8 + tid4)*36 + qg*16 + gid + 8]);
                    uint32_t a2 = fu(sR[(kk*8 + tid4 + 4)*36 + qg*16 + gid]);
                    uint32_t a3 = fu(sR[(kk*8 + tid4 + 4)*36 + qg*16 + gid + 8]);
                    #pragma unroll
                    for (int nt = 0; nt < 5; nt++) {
                        int vv = vg*40 + nt*8 + gid;
                        uint32_t b0 = fu(sV[(kk*8 + tid4)*328 + vv]);
                        uint32_t b1 = fu(sV[(kk*8 + tid4 + 4)*328 + vv]);
                        mma_tf32(sc[nt], a0, a1, a2, a3, b0, b1);
                    }
                }
                #pragma unroll
                for (int nt = 0; nt < 5; nt++) {
                    int q = qg*16 + gid, v = vg*40 + nt*8 + 2*tid4;
                    *(float2*)&sP[q*328 + v]     = make_float2(sc[nt].x, sc[nt].y);
                    *(float2*)&sP[(q+8)*328 + v] = make_float2(sc[nt].z, sc[nt].w);
                }
            }
            __syncthreads();

            // ---- softmax: 2 rows per warp (base-2, Mt pre-scaled by log2e) ----
            #pragma unroll
            for (int i = 0; i < 2; i++) {
                int row = warp*2 + i;
                float a[10];
                #pragma unroll
                for (int j = 0; j < 10; j++) a[j] = sP[row*328 + lane + 32*j];
                float m = a[0];
                #pragma unroll
                for (int j = 1; j < 10; j++) m = fmaxf(m, a[j]);
                #pragma unroll
                for (int o = 16; o > 0; o >>= 1) m = fmaxf(m, __shfl_xor_sync(~0u, m, o));
                float s = 0.f;
                #pragma unroll
                for (int j = 0; j < 10; j++) { a[j] = exp2f(a[j] - m); s += a[j]; }
                #pragma unroll
                for (int o = 16; o > 0; o >>= 1) s += __shfl_xor_sync(~0u, s, o);
                float inv = 1.f / s;
                #pragma unroll
                for (int j = 0; j < 10; j++)
                    sP[row*328 + lane + 32*j] = __uint_as_float(f2tf32(a[j]*inv));
            }
            __syncthreads();

            // ---- attend: warp = 16c x 16q, split-K 2 (cg4 x qg2 x kh2) ----
            {
                int cg = warp & 3, qg = (warp >> 2) & 1, kh = warp >> 3;
                float4 oc[2];
                oc[0] = make_float4(0.f,0.f,0.f,0.f);
                oc[1] = make_float4(0.f,0.f,0.f,0.f);
                #pragma unroll 4
                for (int k = 0; k < 20; k++) {
                    int kb = kh*160 + k*8;
                    uint32_t a0 = fu(sV[(cg*16 + gid)*328 + kb + tid4]);
                    uint32_t a1 = fu(sV[(cg*16 + gid + 8)*328 + kb + tid4]);
                    uint32_t a2 = fu(sV[(cg*16 + gid)*328 + kb + tid4 + 4]);
                    uint32_t a3 = fu(sV[(cg*16 + gid + 8)*328 + kb + tid4 + 4]);
                    #pragma unroll
                    for (int nt = 0; nt < 2; nt++) {
                        int prow = qg*16 + nt*8 + gid;
                        uint32_t b0 = fu(sP[prow*328 + kb + tid4]);
                        uint32_t b1 = fu(sP[prow*328 + kb + tid4 + 4]);
                        mma_tf32(oc[nt], a0, a1, a2, a3, b0, b1);
                    }
                }
                if (kh == 0) {
                    #pragma unroll
                    for (int nt = 0; nt < 2; nt++) {
                        int c = cg*16 + gid, q = qg*16 + nt*8 + 2*tid4;
                        *(float2*)&sR[c*36 + q]     = make_float2(oc[nt].x, oc[nt].y);
                        *(float2*)&sR[(c+8)*36 + q] = make_float2(oc[nt].z, oc[nt].w);
                    }
                }
                __syncthreads();
                if (kh == 1) {
                    #pragma unroll
                    for (int nt = 0; nt < 2; nt++) {
                        int c = cg*16 + gid, q = qg*16 + nt*8 + 2*tid4;
                        float2 r0 = *(const float2*)&sR[c*36 + q];
                        float2 r1 = *(const float2*)&sR[(c+8)*36 + q];
                        uint2 w0 = make_uint2(f2tf32(oc[nt].x + r0.x), f2tf32(oc[nt].y + r0.y));
                        uint2 w1 = make_uint2(f2tf32(oc[nt].z + r1.x), f2tf32(oc[nt].w + r1.y));
                        *(uint2*)(outg + (size_t)c*HW + q0 + q)     = w0;
                        *(uint2*)(outg + (size_t)(c+8)*HW + q0 + q) = w1;
                    }
                }
            }
        }
        __syncthreads();
    }
}

// ---------------------------------------------------------------------------
// Kernel 3: tf32 implicit-GEMM 3x3 conv (unchanged).
// ---------------------------------------------------------------------------
#define PLANE 728
#define SIN_U32 (16*PLANE)              // 11648
#define SW_U32  (9*64*18)               // 10368
#define STAGE_U32 (SIN_U32 + SW_U32)    // 22016
#define CONV_SMEM (STAGE_U32*2*4)       // 176128 bytes

template<int CIN, bool FUSE>
__global__ __launch_bounds__(512, 1)
void kconv(const uint32_t* __restrict__ in1u, const uint32_t* __restrict__ in1d,
           const uint32_t* __restrict__ in2u, const uint32_t* __restrict__ in2d,
           const uint32_t* __restrict__ wpu,  const uint32_t* __restrict__ wpd,
           void* __restrict__ outu, void* __restrict__ outd) {
    extern __shared__ uint32_t csm[];

    int tid  = threadIdx.x;
    int lane = tid & 31, warp = tid >> 5;
    int x0 = blockIdx.x * 64;
    int y0 = blockIdx.y * 8;
    int z  = blockIdx.z;
    int b  = z & 1, st = z >> 1;
    size_t bCHW = (size_t)b*CHW;

    const uint32_t* in1 = st ? in1d : in1u;
    const uint32_t* in2 = st ? in2d : in2u;
    const uint32_t* wp  = st ? wpd  : wpu;
    void* outv          = st ? outd : outu;

    int warp_o = warp & 1;
    int warp_y = warp >> 1;
    int lq = lane >> 2;
    int lr = lane & 3;

    uint32_t s_base = (uint32_t)__cvta_generic_to_shared(csm);
    const int NCH = CIN/16;

    auto stage = [&](int cb, int bufi) {
        uint32_t sb = s_base + bufi*STAGE_U32*4;
        for (int i = tid; i < 2880; i += 512) {
            int c   = i / 180;
            int rem = i % 180;
            int r   = rem / 18;
            int q   = rem % 18;
            int gy = y0 + r - 1;
            int gx = x0 - 4 + q*4;
            uint32_t ok = (gy >= 0 && gy < HH && gx >= 0 && gx < WW) ? 16u : 0u;
            int cg = cb*16 + c;
            const uint32_t* plane;
            if (CIN == 128 && cg >= 64) plane = in2 + bCHW + (size_t)(cg - 64)*HW;
            else                        plane = in1 + bCHW + (size_t)cg*HW;
            const uint32_t* gsrc = ok ? (plane + gy*WW + gx) : plane;
            cp16(sb + (c*PLANE + r*72 + q*4)*4, gsrc, ok);
        }
        const uint32_t* wsrc = wp + cb*SW_U32;
        for (int i = tid; i < SW_U32/4; i += 512)
            cp16(sb + (SIN_U32 + i*4)*4, wsrc + i*4, 16);
    };

    float4 acc[2][8];
    #pragma unroll
    for (int mt = 0; mt < 2; mt++)
        #pragma unroll
        for (int nt = 0; nt < 8; nt++) acc[mt][nt] = make_float4(0.f,0.f,0.f,0.f);

    stage(0, 0);
    asm volatile("cp.async.commit_group;" ::: "memory");

    for (int cb = 0; cb < NCH; cb++) {
        if (cb + 1 < NCH) {
            stage(cb + 1, (cb + 1) & 1);
            asm volatile("cp.async.commit_group;" ::: "memory");
            asm volatile("cp.async.wait_group 1;" ::: "memory");
        } else {
            asm volatile("cp.async.wait_group 0;" ::: "memory");
        }
        __syncthreads();

        const uint32_t* sin_ = csm + (cb & 1)*STAGE_U32;
        const uint32_t* sw_  = sin_ + SIN_U32;

        #pragma unroll
        for (int t = 0; t < 9; t++) {
            int ky = t/3, kx = t - ky*3;
            int row = warp_y + ky;
            int bbase = row*72 + kx + 3 + lq;
            #pragma unroll
            for (int s = 0; s < 2; s++) {
                int aoff = (t*64 + warp_o*32)*18 + s*8 + 2*lr;
                uint2 a00 = *(const uint2*)&sw_[aoff + lq*18];
                uint2 a01 = *(const uint2*)&sw_[aoff + (lq+8)*18];
                uint2 a10 = *(const uint2*)&sw_[aoff + (lq+16)*18];
                uint2 a11 = *(const uint2*)&sw_[aoff + (lq+24)*18];
                int p0 = (s*8 + lr)*PLANE + bbase;
                int p1 = p0 + 4*PLANE;
                #pragma unroll
                for (int nt = 0; nt < 8; nt++) {
                    uint32_t b0 = sin_[p0 + 8*nt];
                    uint32_t b1 = sin_[p1 + 8*nt];
                    mma_tf32(acc[0][nt], a00.x, a01.x, a00.y, a01.y, b0, b1);
                    mma_tf32(acc[1][nt], a10.x, a11.x, a10.y, a11.y, b0, b1);
                }
            }
        }
        __syncthreads();
    }

    int y = y0 + warp_y;
    #pragma unroll
    for (int mt = 0; mt < 2; mt++) {
        int o_lo = warp_o*32 + mt*16 + lq;
        #pragma unroll
        for (int nt = 0; nt < 8; nt++) {
            int x = x0 + nt*8 + 2*lr;
            float4 v = acc[mt][nt];
            size_t off = bCHW + (size_t)o_lo*HW + (size_t)y*WW + x;
            if (FUSE) {
                uint32_t* outp = (uint32_t*)outv;
                uint2 r0 = make_uint2(f2tf32(fmaxf(v.x, 0.f)), f2tf32(fmaxf(v.y, 0.f)));
                uint2 r1 = make_uint2(f2tf32(fmaxf(v.z, 0.f)), f2tf32(fmaxf(v.w, 0.f)));
                *(uint2*)(outp + off)            = r0;
                *(uint2*)(outp + off + 8*HW)     = r1;
            } else {
                float* outp = (float*)outv;
                *(float2*)(outp + off)           = make_float2(v.x, v.y);
                *(float2*)(outp + off + 8*HW)    = make_float2(v.z, v.w);
            }
        }
    }
}

// ---------------------------------------------------------------------------
extern "C" void kernel_launch(void* const* d_in, const int* in_sizes, int n_in,
                              void* d_out, int out_size) {
    const float* u   = (const float*)d_in[0];
    const float* d   = (const float*)d_in[1];
    const float* Wu1 = (const float*)d_in[2];
    const float* Wu2 = (const float*)d_in[3];
    const float* Wd1 = (const float*)d_in[4];
    const float* Wd2 = (const float*)d_in[5];
    const float* W1a = (const float*)d_in[6];
    const float* W1b = (const float*)d_in[7];
    const float* W2a = (const float*)d_in[8];
    const float* W2b = (const float*)d_in[9];
    float* out = (float*)d_out;

    cudaFuncSetAttribute(kattn, cudaFuncAttributeMaxDynamicSharedMemorySize, ATTN_SMEM);
    cudaFuncSetAttribute(kconv<128, true>,  cudaFuncAttributeMaxDynamicSharedMemorySize, CONV_SMEM);
    cudaFuncSetAttribute(kconv<64, false>,  cudaFuncAttributeMaxDynamicSharedMemorySize, CONV_SMEM);

    uint32_t *pbuf0, *pbuf1, *pt0, *pt1, *putf, *pdtf;
    uint32_t *pw1a, *pw2a, *pw1b, *pw2b;
    cudaGetSymbolAddress((void**)&pbuf0, g_buf);   pbuf1 = pbuf0 + TENSOR_ELEMS;
    cudaGetSymbolAddress((void**)&pt0,   g_t);     pt1   = pt0   + TENSOR_ELEMS;
    cudaGetSymbolAddress((void**)&putf,  g_utf);
    cudaGetSymbolAddress((void**)&pdtf,  g_dtf);
    cudaGetSymbolAddress((void**)&pw1a,  g_wp1a);
    cudaGetSymbolAddress((void**)&pw2a,  g_wp2a);
    cudaGetSymbolAddress((void**)&pw1b,  g_wp1b);
    cudaGetSymbolAddress((void**)&pw2b,  g_wp2b);

    kprepin<<<2048, 256>>>(u, d);
    kprepwAll<<<972, 256>>>(W1a, W2a, W1b, W2b);
    kcomputeM2<<<2, 256>>>(Wu1, Wd2, Wd1, Wu2);

    kattn<<<BB*HH, 512, ATTN_SMEM>>>(0);

    dim3 grid(WW/64, HH/8, 4);
    kconv<128, true><<<grid, 512, CONV_SMEM>>>(putf, pdtf, pbuf0, pbuf1,
                                               pw1a, pw2a, pt0, pt1);
    kconv<64, false><<<grid, 512, CONV_SMEM>>>(pt0, pt1, pt0, pt1,
                                               pw1b, pw2b, out, out + TENSOR_ELEMS);
}

// round 11
// speedup vs baseline: 1.3561x; 1.2911x over previous
#include <cuda_runtime.h>
#include <cuda_fp16.h>
#include <cstddef>
#include <cstdint>

#define HH 320
#define WW 320
#define CC 64
#define BB 2
#define HW (HH*WW)              // 102400
#define CHW ((size_t)CC*HW)     // 6553600
#define TENSOR_ELEMS (BB*CHW)   // 13107200

// Scratch (static device arrays; no allocation allowed)
__device__ uint32_t g_Mth[2*CC*32];          // fp16x2 Mt pairs: [dir][b][ap]
__device__ uint32_t g_buf[2][TENSOR_ELEMS];  // buffer_d, buffer_u (tf32 bits)
__device__ uint32_t g_t[2][TENSOR_ELEMS];    // relu(conv1) intermediates (tf32 bits)
__device__ uint32_t g_utf[TENSOR_ELEMS];     // tf32(u)
__device__ uint32_t g_dtf[TENSOR_ELEMS];     // tf32(d)
// pre-permuted tf32 weights: [chunk][tap][o][18]
__device__ uint32_t g_wp1a[8*9*64*18];
__device__ uint32_t g_wp2a[8*9*64*18];
__device__ uint32_t g_wp1b[4*9*64*18];
__device__ uint32_t g_wp2b[4*9*64*18];

__device__ __forceinline__ uint32_t f2tf32(float f) {
    uint32_t r; asm("cvt.rna.tf32.f32 %0, %1;" : "=r"(r) : "f"(f)); return r;
}
__device__ __forceinline__ void mma_tf32(float4& d,
        uint32_t a0, uint32_t a1, uint32_t a2, uint32_t a3,
        uint32_t b0, uint32_t b1) {
    asm("mma.sync.aligned.m16n8k8.row.col.f32.tf32.tf32.f32 "
        "{%0,%1,%2,%3}, {%4,%5,%6,%7}, {%8,%9}, {%0,%1,%2,%3};"
        : "+f"(d.x), "+f"(d.y), "+f"(d.z), "+f"(d.w)
        : "r"(a0), "r"(a1), "r"(a2), "r"(a3), "r"(b0), "r"(b1));
}
__device__ __forceinline__ void mma_f16(float4& d,
        uint32_t a0, uint32_t a1, uint32_t a2, uint32_t a3,
        uint32_t b0, uint32_t b1) {
    asm("mma.sync.aligned.m16n8k16.row.col.f32.f16.f16.f32 "
        "{%0,%1,%2,%3}, {%4,%5,%6,%7}, {%8,%9}, {%0,%1,%2,%3};"
        : "+f"(d.x), "+f"(d.y), "+f"(d.z), "+f"(d.w)
        : "r"(a0), "r"(a1), "r"(a2), "r"(a3), "r"(b0), "r"(b1));
}
__device__ __forceinline__ uint32_t prmt(uint32_t lo, uint32_t hi, uint32_t sel) {
    uint32_t r; asm("prmt.b32 %0, %1, %2, %3;" : "=r"(r) : "r"(lo), "r"(hi), "r"(sel));
    return r;
}
__device__ __forceinline__ void cp16(uint32_t saddr, const void* gaddr, uint32_t sz) {
    asm volatile("cp.async.cg.shared.global [%0], [%1], 16, %2;"
                 :: "r"(saddr), "l"(gaddr), "r"(sz));
}
__device__ __forceinline__ uint32_t h2u(__half2 h) { return *(uint32_t*)&h; }

// ---------------------------------------------------------------------------
// prep: convert u,d to tf32 bit arrays (conv inputs)
// ---------------------------------------------------------------------------
__global__ void kprepin(const float* __restrict__ u, const float* __restrict__ d) {
    for (size_t i = (size_t)blockIdx.x*256 + threadIdx.x; i < TENSOR_ELEMS;
         i += (size_t)gridDim.x*256) {
        g_utf[i] = f2tf32(u[i]);
        g_dtf[i] = f2tf32(d[i]);
    }
}

// ---------------------------------------------------------------------------
// prep: all 4 conv weights in ONE launch
// ---------------------------------------------------------------------------
__device__ __forceinline__ void prepw_one(const float* __restrict__ W,
                                          uint32_t* __restrict__ dst,
                                          int cin, int i) {
    int w    = i % 18;
    int rest = i / 18;
    int o    = rest % 64;
    int rest2= rest / 64;
    int t    = rest2 % 9;
    int chunk= rest2 / 9;
    uint32_t v = 0;
    if (w < 16) {
        int s = w >> 3, p = w & 7;
        int c = (p >> 1) + ((p & 1) << 2);
        int cinidx = chunk*16 + s*8 + c;
        v = f2tf32(W[(size_t)o*(cin*9) + (size_t)cinidx*9 + t]);
    }
    dst[i] = v;
}

#define WPA (8*9*64*18)   // 82944
#define WPB (4*9*64*18)   // 41472

__global__ void kprepwAll(const float* __restrict__ W1a, const float* __restrict__ W2a,
                          const float* __restrict__ W1b, const float* __restrict__ W2b) {
    int total = 2*WPA + 2*WPB;
    for (int i = blockIdx.x*256 + threadIdx.x; i < total; i += gridDim.x*256) {
        if (i < WPA)                 prepw_one(W1a, g_wp1a, 128, i);
        else if (i < 2*WPA)          prepw_one(W2a, g_wp2a, 128, i - WPA);
        else if (i < 2*WPA + WPB)    prepw_one(W1b, g_wp1b, 64,  i - 2*WPA);
        else                         prepw_one(W2b, g_wp2b, 64,  i - 2*WPA - WPB);
    }
}

// ---------------------------------------------------------------------------
// Kernel 1: Mth[dir][b][ap] = half2( log2e*Mt[b][2ap], log2e*Mt[b][2ap+1] )
// where Mt[b][a] = sum_c Wq[c][a]*Wk[c][b]
// ---------------------------------------------------------------------------
__global__ void kcomputeM2(const float* __restrict__ Wu1, const float* __restrict__ Wd2,
                           const float* __restrict__ Wd1, const float* __restrict__ Wu2) {
    __shared__ float sq[64*64];
    __shared__ float sk[64*64];
    int dir = blockIdx.x;
    const float* Wq = dir ? Wd1 : Wu1;
    const float* Wk = dir ? Wu2 : Wd2;
    int t = threadIdx.x;
    for (int i = t; i < 4096; i += 256) { sq[i] = Wq[i]; sk[i] = Wk[i]; }
    __syncthreads();
    const float LOG2E = 1.4426950408889634f;
    for (int i = t; i < 2048; i += 256) {
        int b  = i & 63;
        int ap = i >> 6;
        float s0 = 0.f, s1 = 0.f;
        #pragma unroll 16
        for (int c = 0; c < 64; c++) {
            s0 += sq[c*64 + 2*ap]     * sk[c*64 + b];
            s1 += sq[c*64 + 2*ap + 1] * sk[c*64 + b];
        }
        g_Mth[dir*2048 + b*32 + ap] = h2u(__floats2half2_rn(s0*LOG2E, s1*LOG2E));
    }
}

// ---------------------------------------------------------------------------
// Kernel 2: fp16 tensor-core axial attention, 512 threads, all-warp phases.
// smem (words): sup[32*328], sdp[32*328], sS[32*328], sPh[32*172], sRp[32*40]
// pair layout: word[cp][v] = half2(x[2cp][v], x[2cp+1][v])
// ---------------------------------------------------------------------------
#define SP  328
#define SPH 172
#define SRP 40
#define ATTN_SMEM ((32*SP*3 + 32*SPH + 32*SRP)*4)   // 153088 B

__global__ __launch_bounds__(512)
void kattn(const float* __restrict__ u, const float* __restrict__ d) {
    extern __shared__ uint32_t sm[];
    uint32_t* sup = sm;
    uint32_t* sdp = sm + 32*SP;
    float*    sS  = (float*)(sm + 2*32*SP);
    uint32_t* sPh = sm + 3*32*SP;
    uint32_t* sRp = sPh + 32*SPH;

    int tid  = threadIdx.x;
    int lane = tid & 31, warp = tid >> 5;    // 16 warps
    int gid  = lane >> 2, tid4 = lane & 3;
    int b = blockIdx.x / HH, h = blockIdx.x % HH;
    const float* ubase = u + (size_t)b*CHW + (size_t)h*WW;
    const float* dbase = d + (size_t)b*CHW + (size_t)h*WW;

    // stage pair-packed fp16 rows of both streams
    for (int i = tid; i < 32*80; i += 512) {
        int cp = i / 80, vq = (i % 80)*4;
        float4 ue = *(const float4*)(ubase + (size_t)(2*cp)*HW + vq);
        float4 uo = *(const float4*)(ubase + (size_t)(2*cp+1)*HW + vq);
        float4 de = *(const float4*)(dbase + (size_t)(2*cp)*HW + vq);
        float4 do_ = *(const float4*)(dbase + (size_t)(2*cp+1)*HW + vq);
        uint4 wu, wd;
        wu.x = h2u(__floats2half2_rn(ue.x, uo.x));
        wu.y = h2u(__floats2half2_rn(ue.y, uo.y));
        wu.z = h2u(__floats2half2_rn(ue.z, uo.z));
        wu.w = h2u(__floats2half2_rn(ue.w, uo.w));
        wd.x = h2u(__floats2half2_rn(de.x, do_.x));
        wd.y = h2u(__floats2half2_rn(de.y, do_.y));
        wd.z = h2u(__floats2half2_rn(de.z, do_.z));
        wd.w = h2u(__floats2half2_rn(de.w, do_.w));
        *(uint4*)&sup[cp*SP + vq] = wu;
        *(uint4*)&sdp[cp*SP + vq] = wd;
    }

    for (int dir = 0; dir < 2; dir++) {
        const uint32_t* sQ = dir ? sdp : sup;
        const uint32_t* sV = dir ? sup : sdp;
        uint32_t* outg = g_buf[dir] + (size_t)b*CHW + (size_t)h*WW;

        // Mt fp16 fragments for R GEMM: warp = bg(4) x rq(4) -> 16b x 8q
        const uint32_t* Mth = g_Mth + dir*2048;
        int bg = warp & 3, rq = warp >> 2;
        int r = bg*16 + gid;
        uint32_t am[4][4];
        #pragma unroll
        for (int kk = 0; kk < 4; kk++) {
            am[kk][0] = Mth[r*32 + kk*8 + tid4];
            am[kk][1] = Mth[(r+8)*32 + kk*8 + tid4];
            am[kk][2] = Mth[r*32 + kk*8 + tid4 + 4];
            am[kk][3] = Mth[(r+8)*32 + kk*8 + tid4 + 4];
        }

        for (int q0 = 0; q0 < WW; q0 += 32) {
            __syncthreads();

            // ---- R[b][q]: 16b x 8q per warp, K=64 (4 fp16 k-steps) ----
            {
                float4 rc = make_float4(0.f,0.f,0.f,0.f);
                int qc = q0 + rq*8 + gid;
                #pragma unroll
                for (int kk = 0; kk < 4; kk++) {
                    uint32_t b0 = sQ[(kk*8 + tid4)*SP + qc];
                    uint32_t b1 = sQ[(kk*8 + tid4 + 4)*SP + qc];
                    mma_f16(rc, am[kk][0], am[kk][1], am[kk][2], am[kk][3], b0, b1);
                }
                __half* rh = (__half*)sRp;
                int bp  = bg*8 + (gid >> 1);
                int par = gid & 1;
                int qq  = rq*8 + 2*tid4;
                rh[(bp*SRP + qq)*2 + par]         = __float2half_rn(rc.x);
                rh[(bp*SRP + qq + 1)*2 + par]     = __float2half_rn(rc.y);
                rh[((bp+4)*SRP + qq)*2 + par]     = __float2half_rn(rc.z);
                rh[((bp+4)*SRP + qq + 1)*2 + par] = __float2half_rn(rc.w);
            }
            __syncthreads();

            // ---- S[q][v]: warp = qg(2) x vg(8) -> 16q x 40v, K=64 ----
            {
                int qg = warp >> 3, vg = warp & 7;
                float4 sc[5];
                #pragma unroll
                for (int nt = 0; nt < 5; nt++) sc[nt] = make_float4(0.f,0.f,0.f,0.f);
                #pragma unroll
                for (int kk = 0; kk < 4; kk++) {
                    uint32_t a0 = sRp[(kk*8 + tid4)*SRP + qg*16 + gid];
                    uint32_t a1 = sRp[(kk*8 + tid4)*SRP + qg*16 + gid + 8];
                    uint32_t a2 = sRp[(kk*8 + tid4 + 4)*SRP + qg*16 + gid];
                    uint32_t a3 = sRp[(kk*8 + tid4 + 4)*SRP + qg*16 + gid + 8];
                    #pragma unroll
                    for (int nt = 0; nt < 5; nt++) {
                        int vv = vg*40 + nt*8 + gid;
                        uint32_t b0 = sV[(kk*8 + tid4)*SP + vv];
                        uint32_t b1 = sV[(kk*8 + tid4 + 4)*SP + vv];
                        mma_f16(sc[nt], a0, a1, a2, a3, b0, b1);
                    }
                }
                #pragma unroll
                for (int nt = 0; nt < 5; nt++) {
                    int q = qg*16 + gid, vv = vg*40 + nt*8 + 2*tid4;
                    *(float2*)&sS[q*SP + vv]     = make_float2(sc[nt].x, sc[nt].y);
                    *(float2*)&sS[(q+8)*SP + vv] = make_float2(sc[nt].z, sc[nt].w);
                }
            }
            __syncthreads();

            // ---- softmax: 2 rows/warp; base-2 (Mt pre-scaled); P -> fp16 pairs ----
            #pragma unroll
            for (int i = 0; i < 2; i++) {
                int row = warp*2 + i;
                float2 a[5];
                #pragma unroll
                for (int j = 0; j < 5; j++)
                    a[j] = *(const float2*)&sS[row*SP + 2*lane + 64*j];
                float m = a[0].x;
                #pragma unroll
                for (int j = 0; j < 5; j++) { m = fmaxf(m, a[j].x); m = fmaxf(m, a[j].y); }
                #pragma unroll
                for (int o = 16; o > 0; o >>= 1) m = fmaxf(m, __shfl_xor_sync(~0u, m, o));
                float s = 0.f;
                #pragma unroll
                for (int j = 0; j < 5; j++) {
                    a[j].x = exp2f(a[j].x - m); a[j].y = exp2f(a[j].y - m);
                    s += a[j].x + a[j].y;
                }
                #pragma unroll
                for (int o = 16; o > 0; o >>= 1) s += __shfl_xor_sync(~0u, s, o);
                float inv = 1.f / s;
                #pragma unroll
                for (int j = 0; j < 5; j++)
                    sPh[row*SPH + lane + 32*j] =
                        h2u(__floats2half2_rn(a[j].x*inv, a[j].y*inv));
            }
            __syncthreads();

            // ---- attend: warp = cg(4) x aqg(2) x kh(2) -> 16c x 16q, K=160 ----
            {
                int cg = warp & 3, aqg = (warp >> 2) & 1, kh = warp >> 3;
                int cp0 = cg*8 + (gid >> 1);
                uint32_t sel = (gid & 1) ? 0x7632u : 0x5410u;
                float4 oc[2];
                oc[0] = make_float4(0.f,0.f,0.f,0.f);
                oc[1] = make_float4(0.f,0.f,0.f,0.f);
                #pragma unroll 2
                for (int kk = 0; kk < 10; kk++) {
                    int kb = kh*160 + kk*16;
                    uint2 w0 = *(const uint2*)&sV[cp0*SP + kb + 2*tid4];
                    uint2 w1 = *(const uint2*)&sV[(cp0+4)*SP + kb + 2*tid4];
                    uint2 w2 = *(const uint2*)&sV[cp0*SP + kb + 2*tid4 + 8];
                    uint2 w3 = *(const uint2*)&sV[(cp0+4)*SP + kb + 2*tid4 + 8];
                    uint32_t a0 = prmt(w0.x, w0.y, sel);
                    uint32_t a1 = prmt(w1.x, w1.y, sel);
                    uint32_t a2 = prmt(w2.x, w2.y, sel);
                    uint32_t a3 = prmt(w3.x, w3.y, sel);
                    int vp = (kb >> 1) + tid4;
                    #pragma unroll
                    for (int nt = 0; nt < 2; nt++) {
                        int q = aqg*16 + nt*8 + gid;
                        uint32_t b0 = sPh[q*SPH + vp];
                        uint32_t b1 = sPh[q*SPH + vp + 4];
                        mma_f16(oc[nt], a0, a1, a2, a3, b0, b1);
                    }
                }
                float* sO = sS;   // reuse score buffer for split-K reduce
                if (kh == 0) {
                    #pragma unroll
                    for (int nt = 0; nt < 2; nt++) {
                        int c = cg*16 + gid, q = aqg*16 + nt*8 + 2*tid4;
                        *(float2*)&sO[c*40 + q]     = make_float2(oc[nt].x, oc[nt].y);
                        *(float2*)&sO[(c+8)*40 + q] = make_float2(oc[nt].z, oc[nt].w);
                    }
                }
                __syncthreads();
                if (kh == 1) {
                    #pragma unroll
                    for (int nt = 0; nt < 2; nt++) {
                        int c = cg*16 + gid, q = aqg*16 + nt*8 + 2*tid4;
                        float2 r0 = *(const float2*)&sO[c*40 + q];
                        float2 r1 = *(const float2*)&sO[(c+8)*40 + q];
                        uint2 w0 = make_uint2(f2tf32(oc[nt].x + r0.x), f2tf32(oc[nt].y + r0.y));
                        uint2 w1 = make_uint2(f2tf32(oc[nt].z + r1.x), f2tf32(oc[nt].w + r1.y));
                        *(uint2*)(outg + (size_t)c*HW + q0 + q)     = w0;
                        *(uint2*)(outg + (size_t)(c+8)*HW + q0 + q) = w1;
                    }
                }
            }
        }
        __syncthreads();
    }
}

// ---------------------------------------------------------------------------
// Kernel 3: tf32 implicit-GEMM 3x3 conv (unchanged from R10).
// ---------------------------------------------------------------------------
#define PLANE 728
#define SIN_U32 (16*PLANE)              // 11648
#define SW_U32  (9*64*18)               // 10368
#define STAGE_U32 (SIN_U32 + SW_U32)    // 22016
#define CONV_SMEM (STAGE_U32*2*4)       // 176128 bytes

template<int CIN, bool FUSE>
__global__ __launch_bounds__(512, 1)
void kconv(const uint32_t* __restrict__ in1u, const uint32_t* __restrict__ in1d,
           const uint32_t* __restrict__ in2u, const uint32_t* __restrict__ in2d,
           const uint32_t* __restrict__ wpu,  const uint32_t* __restrict__ wpd,
           void* __restrict__ outu, void* __restrict__ outd) {
    extern __shared__ uint32_t csm[];

    int tid  = threadIdx.x;
    int lane = tid & 31, warp = tid >> 5;
    int x0 = blockIdx.x * 64;
    int y0 = blockIdx.y * 8;
    int z  = blockIdx.z;
    int b  = z & 1, st = z >> 1;
    size_t bCHW = (size_t)b*CHW;

    const uint32_t* in1 = st ? in1d : in1u;
    const uint32_t* in2 = st ? in2d : in2u;
    const uint32_t* wp  = st ? wpd  : wpu;
    void* outv          = st ? outd : outu;

    int warp_o = warp & 1;
    int warp_y = warp >> 1;
    int lq = lane >> 2;
    int lr = lane & 3;

    uint32_t s_base = (uint32_t)__cvta_generic_to_shared(csm);
    const int NCH = CIN/16;

    auto stage = [&](int cb, int bufi) {
        uint32_t sb = s_base + bufi*STAGE_U32*4;
        for (int i = tid; i < 2880; i += 512) {
            int c   = i / 180;
            int rem = i % 180;
            int r   = rem / 18;
            int q   = rem % 18;
            int gy = y0 + r - 1;
            int gx = x0 - 4 + q*4;
            uint32_t ok = (gy >= 0 && gy < HH && gx >= 0 && gx < WW) ? 16u : 0u;
            int cg = cb*16 + c;
            const uint32_t* plane;
            if (CIN == 128 && cg >= 64) plane = in2 + bCHW + (size_t)(cg - 64)*HW;
            else                        plane = in1 + bCHW + (size_t)cg*HW;
            const uint32_t* gsrc = ok ? (plane + gy*WW + gx) : plane;
            cp16(sb + (c*PLANE + r*72 + q*4)*4, gsrc, ok);
        }
        const uint32_t* wsrc = wp + cb*SW_U32;
        for (int i = tid; i < SW_U32/4; i += 512)
            cp16(sb + (SIN_U32 + i*4)*4, wsrc + i*4, 16);
    };

    float4 acc[2][8];
    #pragma unroll
    for (int mt = 0; mt < 2; mt++)
        #pragma unroll
        for (int nt = 0; nt < 8; nt++) acc[mt][nt] = make_float4(0.f,0.f,0.f,0.f);

    stage(0, 0);
    asm volatile("cp.async.commit_group;" ::: "memory");

    for (int cb = 0; cb < NCH; cb++) {
        if (cb + 1 < NCH) {
            stage(cb + 1, (cb + 1) & 1);
            asm volatile("cp.async.commit_group;" ::: "memory");
            asm volatile("cp.async.wait_group 1;" ::: "memory");
        } else {
            asm volatile("cp.async.wait_group 0;" ::: "memory");
        }
        __syncthreads();

        const uint32_t* sin_ = csm + (cb & 1)*STAGE_U32;
        const uint32_t* sw_  = sin_ + SIN_U32;

        #pragma unroll
        for (int t = 0; t < 9; t++) {
            int ky = t/3, kx = t - ky*3;
            int row = warp_y + ky;
            int bbase = row*72 + kx + 3 + lq;
            #pragma unroll
            for (int s = 0; s < 2; s++) {
                int aoff = (t*64 + warp_o*32)*18 + s*8 + 2*lr;
                uint2 a00 = *(const uint2*)&sw_[aoff + lq*18];
                uint2 a01 = *(const uint2*)&sw_[aoff + (lq+8)*18];
                uint2 a10 = *(const uint2*)&sw_[aoff + (lq+16)*18];
                uint2 a11 = *(const uint2*)&sw_[aoff + (lq+24)*18];
                int p0 = (s*8 + lr)*PLANE + bbase;
                int p1 = p0 + 4*PLANE;
                #pragma unroll
                for (int nt = 0; nt < 8; nt++) {
                    uint32_t b0 = sin_[p0 + 8*nt];
                    uint32_t b1 = sin_[p1 + 8*nt];
                    mma_tf32(acc[0][nt], a00.x, a01.x, a00.y, a01.y, b0, b1);
                    mma_tf32(acc[1][nt], a10.x, a11.x, a10.y, a11.y, b0, b1);
                }
            }
        }
        __syncthreads();
    }

    int y = y0 + warp_y;
    #pragma unroll
    for (int mt = 0; mt < 2; mt++) {
        int o_lo = warp_o*32 + mt*16 + lq;
        #pragma unroll
        for (int nt = 0; nt < 8; nt++) {
            int x = x0 + nt*8 + 2*lr;
            float4 v = acc[mt][nt];
            size_t off = bCHW + (size_t)o_lo*HW + (size_t)y*WW + x;
            if (FUSE) {
                uint32_t* outp = (uint32_t*)outv;
                uint2 r0 = make_uint2(f2tf32(fmaxf(v.x, 0.f)), f2tf32(fmaxf(v.y, 0.f)));
                uint2 r1 = make_uint2(f2tf32(fmaxf(v.z, 0.f)), f2tf32(fmaxf(v.w, 0.f)));
                *(uint2*)(outp + off)            = r0;
                *(uint2*)(outp + off + 8*HW)     = r1;
            } else {
                float* outp = (float*)outv;
                *(float2*)(outp + off)           = make_float2(v.x, v.y);
                *(float2*)(outp + off + 8*HW)    = make_float2(v.z, v.w);
            }
        }
    }
}

// ---------------------------------------------------------------------------
extern "C" void kernel_launch(void* const* d_in, const int* in_sizes, int n_in,
                              void* d_out, int out_size) {
    const float* u   = (const float*)d_in[0];
    const float* d   = (const float*)d_in[1];
    const float* Wu1 = (const float*)d_in[2];
    const float* Wu2 = (const float*)d_in[3];
    const float* Wd1 = (const float*)d_in[4];
    const float* Wd2 = (const float*)d_in[5];
    const float* W1a = (const float*)d_in[6];
    const float* W1b = (const float*)d_in[7];
    const float* W2a = (const float*)d_in[8];
    const float* W2b = (const float*)d_in[9];
    float* out = (float*)d_out;

    cudaFuncSetAttribute(kattn, cudaFuncAttributeMaxDynamicSharedMemorySize, ATTN_SMEM);
    cudaFuncSetAttribute(kconv<128, true>,  cudaFuncAttributeMaxDynamicSharedMemorySize, CONV_SMEM);
    cudaFuncSetAttribute(kconv<64, false>,  cudaFuncAttributeMaxDynamicSharedMemorySize, CONV_SMEM);

    uint32_t *pbuf0, *pbuf1, *pt0, *pt1, *putf, *pdtf;
    uint32_t *pw1a, *pw2a, *pw1b, *pw2b;
    cudaGetSymbolAddress((void**)&pbuf0, g_buf);   pbuf1 = pbuf0 + TENSOR_ELEMS;
    cudaGetSymbolAddress((void**)&pt0,   g_t);     pt1   = pt0   + TENSOR_ELEMS;
    cudaGetSymbolAddress((void**)&putf,  g_utf);
    cudaGetSymbolAddress((void**)&pdtf,  g_dtf);
    cudaGetSymbolAddress((void**)&pw1a,  g_wp1a);
    cudaGetSymbolAddress((void**)&pw2a,  g_wp2a);
    cudaGetSymbolAddress((void**)&pw1b,  g_wp1b);
    cudaGetSymbolAddress((void**)&pw2b,  g_wp2b);

    kprepin<<<2048, 256>>>(u, d);
    kprepwAll<<<972, 256>>>(W1a, W2a, W1b, W2b);
    kcomputeM2<<<2, 256>>>(Wu1, Wd2, Wd1, Wu2);

    kattn<<<BB*HH, 512, ATTN_SMEM>>>(u, d);

    dim3 grid(WW/64, HH/8, 4);
    kconv<128, true><<<grid, 512, CONV_SMEM>>>(putf, pdtf, pbuf0, pbuf1,
                                               pw1a, pw2a, pt0, pt1);
    kconv<64, false><<<grid, 512, CONV_SMEM>>>(pt0, pt1, pt0, pt1,
                                               pw1b, pw2b, out, out + TENSOR_ELEMS);
}

// round 12
// speedup vs baseline: 2.0142x; 1.4853x over previous
#include <cuda_runtime.h>
#include <cuda_fp16.h>
#include <cstddef>
#include <cstdint>

#define HH 320
#define WW 320
#define CC 64
#define BB 2
#define HW (HH*WW)              // 102400
#define CHW ((size_t)CC*HW)     // 6553600
#define TENSOR_ELEMS (BB*CHW)   // 13107200
#define CPHW ((size_t)32*HW)    // pair-planes per batch image

// Scratch (static device arrays; no allocation allowed)
__device__ uint32_t g_Mth[2*CC*32];          // fp16x2 Mt pairs: [dir][b][ap]
__device__ uint32_t g_bufh[2][BB*CPHW];      // attention buffers, fp16 pair-packed
__device__ uint32_t g_th[2][BB*CPHW];        // conv1 outputs, fp16 pair-packed
__device__ uint32_t g_uh[BB*CPHW];           // fp16 pair-packed u
__device__ uint32_t g_dh[BB*CPHW];           // fp16 pair-packed d
// fp16 conv weights: [chunk][tap9][o64][kp8] half2 words
__device__ uint32_t g_wh1a[8*9*64*8];
__device__ uint32_t g_wh2a[8*9*64*8];
__device__ uint32_t g_wh1b[4*9*64*8];
__device__ uint32_t g_wh2b[4*9*64*8];

__device__ __forceinline__ void mma_f16(float4& d,
        uint32_t a0, uint32_t a1, uint32_t a2, uint32_t a3,
        uint32_t b0, uint32_t b1) {
    asm("mma.sync.aligned.m16n8k16.row.col.f32.f16.f16.f32 "
        "{%0,%1,%2,%3}, {%4,%5,%6,%7}, {%8,%9}, {%0,%1,%2,%3};"
        : "+f"(d.x), "+f"(d.y), "+f"(d.z), "+f"(d.w)
        : "r"(a0), "r"(a1), "r"(a2), "r"(a3), "r"(b0), "r"(b1));
}
__device__ __forceinline__ uint32_t prmt(uint32_t lo, uint32_t hi, uint32_t sel) {
    uint32_t r; asm("prmt.b32 %0, %1, %2, %3;" : "=r"(r) : "r"(lo), "r"(hi), "r"(sel));
    return r;
}
__device__ __forceinline__ void cp16(uint32_t saddr, const void* gaddr, uint32_t sz) {
    asm volatile("cp.async.cg.shared.global [%0], [%1], 16, %2;"
                 :: "r"(saddr), "l"(gaddr), "r"(sz));
}
__device__ __forceinline__ uint32_t h2u(__half2 h) { return *(uint32_t*)&h; }

// ---------------------------------------------------------------------------
// prep: pack u,d into fp16 channel-pair planes
// ---------------------------------------------------------------------------
__global__ void kprepin(const float* __restrict__ u, const float* __restrict__ d) {
    for (size_t i = (size_t)blockIdx.x*256 + threadIdx.x; i < (size_t)BB*32*(HW/4);
         i += (size_t)gridDim.x*256) {
        int b  = (int)(i / (32*(HW/4)));
        int cp = (int)((i / (HW/4)) % 32);
        int p4 = (int)(i % (HW/4)) * 4;
        size_t e = (size_t)b*CHW + (size_t)(2*cp)*HW + p4;
        size_t o = e + HW;
        float4 ue = *(const float4*)(u + e);
        float4 uo = *(const float4*)(u + o);
        float4 de = *(const float4*)(d + e);
        float4 do_ = *(const float4*)(d + o);
        uint4 wu, wd;
        wu.x = h2u(__floats2half2_rn(ue.x, uo.x));
        wu.y = h2u(__floats2half2_rn(ue.y, uo.y));
        wu.z = h2u(__floats2half2_rn(ue.z, uo.z));
        wu.w = h2u(__floats2half2_rn(ue.w, uo.w));
        wd.x = h2u(__floats2half2_rn(de.x, do_.x));
        wd.y = h2u(__floats2half2_rn(de.y, do_.y));
        wd.z = h2u(__floats2half2_rn(de.z, do_.z));
        wd.w = h2u(__floats2half2_rn(de.w, do_.w));
        size_t io = (size_t)b*CPHW + (size_t)cp*HW + p4;
        *(uint4*)&g_uh[io] = wu;
        *(uint4*)&g_dh[io] = wd;
    }
}

// ---------------------------------------------------------------------------
// prep: fp16 conv weights. dst[chunk][t][o_store][w8].
// storage w -> kp-pair kpc = (w>>1)+(w&1)*4 (perm for LDS.64 (a0,a2) loads)
// o_store row r in 16-tile -> true out-ch = tb + (r&7)*2 + (r>>3)   (sigma)
// ---------------------------------------------------------------------------
__device__ __forceinline__ void prepwh_one(const float* __restrict__ W,
                                           uint32_t* __restrict__ dst,
                                           int cin, int i) {
    int w      = i & 7;
    int o_st   = (i >> 3) & 63;
    int t      = (i >> 9) % 9;
    int chunk  = i / (9*64*8);
    int kpc = (w >> 1) + (w & 1)*4;
    int c0  = chunk*16 + 2*kpc;
    int r   = o_st & 15, tb = o_st & 48;
    int oc  = tb + (r & 7)*2 + (r >> 3);
    float w0 = W[((size_t)oc*cin + c0)*9 + t];
    float w1 = W[((size_t)oc*cin + c0 + 1)*9 + t];
    dst[i] = h2u(__floats2half2_rn(w0, w1));
}

#define WHA (8*9*64*8)   // 36864
#define WHB (4*9*64*8)   // 18432

__global__ void kprepwAll(const float* __restrict__ W1a, const float* __restrict__ W2a,
                          const float* __restrict__ W1b, const float* __restrict__ W2b) {
    int total = 2*WHA + 2*WHB;
    for (int i = blockIdx.x*256 + threadIdx.x; i < total; i += gridDim.x*256) {
        if (i < WHA)               prepwh_one(W1a, g_wh1a, 128, i);
        else if (i < 2*WHA)        prepwh_one(W2a, g_wh2a, 128, i - WHA);
        else if (i < 2*WHA + WHB)  prepwh_one(W1b, g_wh1b, 64,  i - 2*WHA);
        else                       prepwh_one(W2b, g_wh2b, 64,  i - 2*WHA - WHB);
    }
}

// ---------------------------------------------------------------------------
// Kernel 1: Mth[dir][b][ap] = half2( log2e*Mt[b][2ap], log2e*Mt[b][2ap+1] )
// ---------------------------------------------------------------------------
__global__ void kcomputeM2(const float* __restrict__ Wu1, const float* __restrict__ Wd2,
                           const float* __restrict__ Wd1, const float* __restrict__ Wu2) {
    __shared__ float sq[64*64];
    __shared__ float sk[64*64];
    int dir = blockIdx.x;
    const float* Wq = dir ? Wd1 : Wu1;
    const float* Wk = dir ? Wu2 : Wd2;
    int t = threadIdx.x;
    for (int i = t; i < 4096; i += 256) { sq[i] = Wq[i]; sk[i] = Wk[i]; }
    __syncthreads();
    const float LOG2E = 1.4426950408889634f;
    for (int i = t; i < 2048; i += 256) {
        int b  = i & 63;
        int ap = i >> 6;
        float s0 = 0.f, s1 = 0.f;
        #pragma unroll 16
        for (int c = 0; c < 64; c++) {
            s0 += sq[c*64 + 2*ap]     * sk[c*64 + b];
            s1 += sq[c*64 + 2*ap + 1] * sk[c*64 + b];
        }
        g_Mth[dir*2048 + b*32 + ap] = h2u(__floats2half2_rn(s0*LOG2E, s1*LOG2E));
    }
}

// ---------------------------------------------------------------------------
// Kernel 2: fp16 tensor-core axial attention; outputs fp16 pair-packed buffer.
// ---------------------------------------------------------------------------
#define SP  328
#define SPH 172
#define SRP 40
#define ATTN_SMEM ((32*SP*3 + 32*SPH + 32*SRP)*4)   // 153088 B

__global__ __launch_bounds__(512)
void kattn(const float* __restrict__ u, const float* __restrict__ d) {
    extern __shared__ uint32_t sm[];
    uint32_t* sup = sm;
    uint32_t* sdp = sm + 32*SP;
    float*    sS  = (float*)(sm + 2*32*SP);
    uint32_t* sPh = sm + 3*32*SP;
    uint32_t* sRp = sPh + 32*SPH;

    int tid  = threadIdx.x;
    int lane = tid & 31, warp = tid >> 5;    // 16 warps
    int gid  = lane >> 2, tid4 = lane & 3;
    int b = blockIdx.x / HH, h = blockIdx.x % HH;
    const float* ubase = u + (size_t)b*CHW + (size_t)h*WW;
    const float* dbase = d + (size_t)b*CHW + (size_t)h*WW;

    for (int i = tid; i < 32*80; i += 512) {
        int cp = i / 80, vq = (i % 80)*4;
        float4 ue = *(const float4*)(ubase + (size_t)(2*cp)*HW + vq);
        float4 uo = *(const float4*)(ubase + (size_t)(2*cp+1)*HW + vq);
        float4 de = *(const float4*)(dbase + (size_t)(2*cp)*HW + vq);
        float4 do_ = *(const float4*)(dbase + (size_t)(2*cp+1)*HW + vq);
        uint4 wu, wd;
        wu.x = h2u(__floats2half2_rn(ue.x, uo.x));
        wu.y = h2u(__floats2half2_rn(ue.y, uo.y));
        wu.z = h2u(__floats2half2_rn(ue.z, uo.z));
        wu.w = h2u(__floats2half2_rn(ue.w, uo.w));
        wd.x = h2u(__floats2half2_rn(de.x, do_.x));
        wd.y = h2u(__floats2half2_rn(de.y, do_.y));
        wd.z = h2u(__floats2half2_rn(de.z, do_.z));
        wd.w = h2u(__floats2half2_rn(de.w, do_.w));
        *(uint4*)&sup[cp*SP + vq] = wu;
        *(uint4*)&sdp[cp*SP + vq] = wd;
    }

    for (int dir = 0; dir < 2; dir++) {
        const uint32_t* sQ = dir ? sdp : sup;
        const uint32_t* sV = dir ? sup : sdp;
        uint32_t* outgh = g_bufh[dir] + (size_t)b*CPHW + (size_t)h*WW;

        const uint32_t* Mth = g_Mth + dir*2048;
        int bg = warp & 3, rq = warp >> 2;
        int r = bg*16 + gid;
        uint32_t am[4][4];
        #pragma unroll
        for (int kk = 0; kk < 4; kk++) {
            am[kk][0] = Mth[r*32 + kk*8 + tid4];
            am[kk][1] = Mth[(r+8)*32 + kk*8 + tid4];
            am[kk][2] = Mth[r*32 + kk*8 + tid4 + 4];
            am[kk][3] = Mth[(r+8)*32 + kk*8 + tid4 + 4];
        }

        for (int q0 = 0; q0 < WW; q0 += 32) {
            __syncthreads();

            // ---- R[b][q]: 16b x 8q per warp, K=64 ----
            {
                float4 rc = make_float4(0.f,0.f,0.f,0.f);
                int qc = q0 + rq*8 + gid;
                #pragma unroll
                for (int kk = 0; kk < 4; kk++) {
                    uint32_t b0 = sQ[(kk*8 + tid4)*SP + qc];
                    uint32_t b1 = sQ[(kk*8 + tid4 + 4)*SP + qc];
                    mma_f16(rc, am[kk][0], am[kk][1], am[kk][2], am[kk][3], b0, b1);
                }
                __half* rh = (__half*)sRp;
                int bp  = bg*8 + (gid >> 1);
                int par = gid & 1;
                int qq  = rq*8 + 2*tid4;
                rh[(bp*SRP + qq)*2 + par]         = __float2half_rn(rc.x);
                rh[(bp*SRP + qq + 1)*2 + par]     = __float2half_rn(rc.y);
                rh[((bp+4)*SRP + qq)*2 + par]     = __float2half_rn(rc.z);
                rh[((bp+4)*SRP + qq + 1)*2 + par] = __float2half_rn(rc.w);
            }
            __syncthreads();

            // ---- S[q][v]: warp = qg(2) x vg(8) -> 16q x 40v, K=64 ----
            {
                int qg = warp >> 3, vg = warp & 7;
                float4 sc[5];
                #pragma unroll
                for (int nt = 0; nt < 5; nt++) sc[nt] = make_float4(0.f,0.f,0.f,0.f);
                #pragma unroll
                for (int kk = 0; kk < 4; kk++) {
                    uint32_t a0 = sRp[(kk*8 + tid4)*SRP + qg*16 + gid];
                    uint32_t a1 = sRp[(kk*8 + tid4)*SRP + qg*16 + gid + 8];
                    uint32_t a2 = sRp[(kk*8 + tid4 + 4)*SRP + qg*16 + gid];
                    uint32_t a3 = sRp[(kk*8 + tid4 + 4)*SRP + qg*16 + gid + 8];
                    #pragma unroll
                    for (int nt = 0; nt < 5; nt++) {
                        int vv = vg*40 + nt*8 + gid;
                        uint32_t b0 = sV[(kk*8 + tid4)*SP + vv];
                        uint32_t b1 = sV[(kk*8 + tid4 + 4)*SP + vv];
                        mma_f16(sc[nt], a0, a1, a2, a3, b0, b1);
                    }
                }
                #pragma unroll
                for (int nt = 0; nt < 5; nt++) {
                    int q = qg*16 + gid, vv = vg*40 + nt*8 + 2*tid4;
                    *(float2*)&sS[q*SP + vv]     = make_float2(sc[nt].x, sc[nt].y);
                    *(float2*)&sS[(q+8)*SP + vv] = make_float2(sc[nt].z, sc[nt].w);
                }
            }
            __syncthreads();

            // ---- softmax: 2 rows/warp ----
            #pragma unroll
            for (int i = 0; i < 2; i++) {
                int row = warp*2 + i;
                float2 a[5];
                #pragma unroll
                for (int j = 0; j < 5; j++)
                    a[j] = *(const float2*)&sS[row*SP + 2*lane + 64*j];
                float m = a[0].x;
                #pragma unroll
                for (int j = 0; j < 5; j++) { m = fmaxf(m, a[j].x); m = fmaxf(m, a[j].y); }
                #pragma unroll
                for (int o = 16; o > 0; o >>= 1) m = fmaxf(m, __shfl_xor_sync(~0u, m, o));
                float s = 0.f;
                #pragma unroll
                for (int j = 0; j < 5; j++) {
                    a[j].x = exp2f(a[j].x - m); a[j].y = exp2f(a[j].y - m);
                    s += a[j].x + a[j].y;
                }
                #pragma unroll
                for (int o = 16; o > 0; o >>= 1) s += __shfl_xor_sync(~0u, s, o);
                float inv = 1.f / s;
                #pragma unroll
                for (int j = 0; j < 5; j++)
                    sPh[row*SPH + lane + 32*j] =
                        h2u(__floats2half2_rn(a[j].x*inv, a[j].y*inv));
            }
            __syncthreads();

            // ---- attend: warp = cg(4) x aqg(2) x kh(2); rows = adjacent ch pair ----
            {
                int cg = warp & 3, aqg = (warp >> 2) & 1, kh = warp >> 3;
                int gam = cg*8 + gid;          // channel pair index
                int c0  = 2*gam;               // even channel
                float4 oc[2];
                oc[0] = make_float4(0.f,0.f,0.f,0.f);
                oc[1] = make_float4(0.f,0.f,0.f,0.f);
                #pragma unroll 2
                for (int kk = 0; kk < 10; kk++) {
                    int kb = kh*160 + kk*16;
                    uint2 w0 = *(const uint2*)&sV[gam*SP + kb + 2*tid4];
                    uint2 w1 = *(const uint2*)&sV[gam*SP + kb + 2*tid4 + 8];
                    uint32_t a0 = prmt(w0.x, w0.y, 0x5410u);
                    uint32_t a1 = prmt(w0.x, w0.y, 0x7632u);
                    uint32_t a2 = prmt(w1.x, w1.y, 0x5410u);
                    uint32_t a3 = prmt(w1.x, w1.y, 0x7632u);
                    int vp = (kb >> 1) + tid4;
                    #pragma unroll
                    for (int nt = 0; nt < 2; nt++) {
                        int q = aqg*16 + nt*8 + gid;
                        uint32_t b0 = sPh[q*SPH + vp];
                        uint32_t b1 = sPh[q*SPH + vp + 4];
                        mma_f16(oc[nt], a0, a1, a2, a3, b0, b1);
                    }
                }
                float* sO = sS;   // reuse (64 rows x 40)
                if (kh == 0) {
                    #pragma unroll
                    for (int nt = 0; nt < 2; nt++) {
                        int q = aqg*16 + nt*8 + 2*tid4;
                        *(float2*)&sO[c0*40 + q]     = make_float2(oc[nt].x, oc[nt].y);
                        *(float2*)&sO[(c0+1)*40 + q] = make_float2(oc[nt].z, oc[nt].w);
                    }
                }
                __syncthreads();
                if (kh == 1) {
                    #pragma unroll
                    for (int nt = 0; nt < 2; nt++) {
                        int q = aqg*16 + nt*8 + 2*tid4;
                        float2 r0 = *(const float2*)&sO[c0*40 + q];
                        float2 r1 = *(const float2*)&sO[(c0+1)*40 + q];
                        uint2 wv;
                        wv.x = h2u(__floats2half2_rn(oc[nt].x + r0.x, oc[nt].z + r1.x));
                        wv.y = h2u(__floats2half2_rn(oc[nt].y + r0.y, oc[nt].w + r1.y));
                        *(uint2*)(outgh + (size_t)gam*HW + q0 + q) = wv;
                    }
                }
            }
        }
        __syncthreads();
    }
}

// ---------------------------------------------------------------------------
// Kernel 3: fp16 implicit-GEMM 3x3 conv (m16n8k16), double-buffered cp.async.
// Input planes: fp16 channel-pair words, stride 728 (24 mod 32).
// Weights: [t][o_store][8] half2 with kp perm + sigma rows.
// ---------------------------------------------------------------------------
#define PLH 728
#define SINH (8*PLH)                    // 5824
#define SWH  (9*64*8)                   // 4608
#define STH  (SINH + SWH)               // 10432
#define CONVH_SMEM (STH*2*4)            // 83456 bytes

template<int CIN, bool FUSE>
__global__ __launch_bounds__(512, 1)
void kconvH(const uint32_t* __restrict__ in1u, const uint32_t* __restrict__ in1d,
            const uint32_t* __restrict__ in2u, const uint32_t* __restrict__ in2d,
            const uint32_t* __restrict__ wpu,  const uint32_t* __restrict__ wpd,
            void* __restrict__ outu, void* __restrict__ outd) {
    extern __shared__ uint32_t csm[];

    int tid  = threadIdx.x;
    int lane = tid & 31, warp = tid >> 5;
    int x0 = blockIdx.x * 64;
    int y0 = blockIdx.y * 8;
    int z  = blockIdx.z;
    int b  = z & 1, st = z >> 1;

    const uint32_t* in1 = (st ? in1d : in1u) + (size_t)b*CPHW;
    const uint32_t* in2 = (CIN == 128) ? ((st ? in2d : in2u) + (size_t)b*CPHW) : nullptr;
    const uint32_t* wp  = st ? wpd  : wpu;
    void* outv          = st ? outd : outu;

    int warp_o = warp & 1;
    int warp_y = warp >> 1;         // 0..7
    int lq = lane >> 2;             // pixel group / A row
    int lr = lane & 3;              // k group

    uint32_t s_base = (uint32_t)__cvta_generic_to_shared(csm);
    const int NCH = CIN/16;

    auto stage = [&](int cb, int bufi) {
        uint32_t sb = s_base + bufi*STH*4;
        // input: 8 pair-planes x 10 rows x 18 quads
        for (int i = tid; i < 1440; i += 512) {
            int c   = i / 180;
            int rem = i % 180;
            int r   = rem / 18;
            int q   = rem % 18;
            int gy = y0 + r - 1;
            int gx = x0 - 4 + q*4;
            uint32_t ok = (gy >= 0 && gy < HH && gx >= 0 && gx < WW) ? 16u : 0u;
            int cpg = cb*8 + c;
            const uint32_t* plane = (CIN == 128 && cpg >= 32)
                                  ? in2 + (size_t)(cpg - 32)*HW
                                  : in1 + (size_t)cpg*HW;
            const uint32_t* gsrc = ok ? (plane + gy*WW + gx) : plane;
            cp16(sb + (c*PLH + r*72 + q*4)*4, gsrc, ok);
        }
        const uint32_t* wsrc = wp + cb*SWH;
        for (int i = tid; i < SWH/4; i += 512)
            cp16(sb + (SINH + i*4)*4, wsrc + i*4, 16);
    };

    float4 acc[2][8];
    #pragma unroll
    for (int mt = 0; mt < 2; mt++)
        #pragma unroll
        for (int nt = 0; nt < 8; nt++) acc[mt][nt] = make_float4(0.f,0.f,0.f,0.f);

    stage(0, 0);
    asm volatile("cp.async.commit_group;" ::: "memory");

    for (int cb = 0; cb < NCH; cb++) {
        if (cb + 1 < NCH) {
            stage(cb + 1, (cb + 1) & 1);
            asm volatile("cp.async.commit_group;" ::: "memory");
            asm volatile("cp.async.wait_group 1;" ::: "memory");
        } else {
            asm volatile("cp.async.wait_group 0;" ::: "memory");
        }
        __syncthreads();

        const uint32_t* sin_ = csm + (cb & 1)*STH;
        const uint32_t* sw_  = sin_ + SINH;

        #pragma unroll
        for (int t = 0; t < 9; t++) {
            int ky = t/3, kx = t - ky*3;
            int row = warp_y + ky;
            int bbase = row*72 + kx + 3 + lq;
            // A fragments: rows lq / lq+8 of each 16-tile; (a0,a2)/(a1,a3) via LDS.64
            uint2 ae0 = *(const uint2*)&sw_[(t*64 + warp_o*32 + lq)*8 + 2*lr];
            uint2 ao0 = *(const uint2*)&sw_[(t*64 + warp_o*32 + lq + 8)*8 + 2*lr];
            uint2 ae1 = *(const uint2*)&sw_[(t*64 + warp_o*32 + 16 + lq)*8 + 2*lr];
            uint2 ao1 = *(const uint2*)&sw_[(t*64 + warp_o*32 + 16 + lq + 8)*8 + 2*lr];
            int p0 = lr*PLH + bbase;
            int p1 = p0 + 4*PLH;
            #pragma unroll
            for (int nt = 0; nt < 8; nt++) {
                uint32_t b0 = sin_[p0 + 8*nt];
                uint32_t b1 = sin_[p1 + 8*nt];
                mma_f16(acc[0][nt], ae0.x, ao0.x, ae0.y, ao0.y, b0, b1);
                mma_f16(acc[1][nt], ae1.x, ao1.x, ae1.y, ao1.y, b0, b1);
            }
        }
        __syncthreads();
    }

    // ---- writeback: rows = adjacent channel pair (sigma) ----
    int y = y0 + warp_y;
    #pragma unroll
    for (int mt = 0; mt < 2; mt++) {
        int tb  = warp_o*32 + mt*16;
        int ch0 = tb + 2*lq;
        int cp  = (tb >> 1) + lq;
        #pragma unroll
        for (int nt = 0; nt < 8; nt++) {
            int x = x0 + nt*8 + 2*lr;
            float4 v = acc[mt][nt];
            if (FUSE) {
                uint32_t* outp = (uint32_t*)outv;
                uint2 wv;
                wv.x = h2u(__floats2half2_rn(fmaxf(v.x, 0.f), fmaxf(v.z, 0.f)));
                wv.y = h2u(__floats2half2_rn(fmaxf(v.y, 0.f), fmaxf(v.w, 0.f)));
                *(uint2*)(outp + (size_t)b*CPHW + (size_t)cp*HW + (size_t)y*WW + x) = wv;
            } else {
                float* outp = (float*)outv;
                size_t off = (size_t)b*CHW + (size_t)ch0*HW + (size_t)y*WW + x;
                *(float2*)(outp + off)      = make_float2(v.x, v.y);
                *(float2*)(outp + off + HW) = make_float2(v.z, v.w);
            }
        }
    }
}

// ---------------------------------------------------------------------------
extern "C" void kernel_launch(void* const* d_in, const int* in_sizes, int n_in,
                              void* d_out, int out_size) {
    const float* u   = (const float*)d_in[0];
    const float* d   = (const float*)d_in[1];
    const float* Wu1 = (const float*)d_in[2];
    const float* Wu2 = (const float*)d_in[3];
    const float* Wd1 = (const float*)d_in[4];
    const float* Wd2 = (const float*)d_in[5];
    const float* W1a = (const float*)d_in[6];
    const float* W1b = (const float*)d_in[7];
    const float* W2a = (const float*)d_in[8];
    const float* W2b = (const float*)d_in[9];
    float* out = (float*)d_out;

    cudaFuncSetAttribute(kattn, cudaFuncAttributeMaxDynamicSharedMemorySize, ATTN_SMEM);
    cudaFuncSetAttribute(kconvH<128, true>,  cudaFuncAttributeMaxDynamicSharedMemorySize, CONVH_SMEM);
    cudaFuncSetAttribute(kconvH<64, false>,  cudaFuncAttributeMaxDynamicSharedMemorySize, CONVH_SMEM);

    uint32_t *pbuf0, *pbuf1, *pt0, *pt1, *puh, *pdh;
    uint32_t *pw1a, *pw2a, *pw1b, *pw2b;
    cudaGetSymbolAddress((void**)&pbuf0, g_bufh);  pbuf1 = pbuf0 + BB*CPHW;
    cudaGetSymbolAddress((void**)&pt0,   g_th);    pt1   = pt0   + BB*CPHW;
    cudaGetSymbolAddress((void**)&puh,   g_uh);
    cudaGetSymbolAddress((void**)&pdh,   g_dh);
    cudaGetSymbolAddress((void**)&pw1a,  g_wh1a);
    cudaGetSymbolAddress((void**)&pw2a,  g_wh2a);
    cudaGetSymbolAddress((void**)&pw1b,  g_wh1b);
    cudaGetSymbolAddress((void**)&pw2b,  g_wh2b);

    kprepin<<<2048, 256>>>(u, d);
    kprepwAll<<<432, 256>>>(W1a, W2a, W1b, W2b);
    kcomputeM2<<<2, 256>>>(Wu1, Wd2, Wd1, Wu2);

    kattn<<<BB*HH, 512, ATTN_SMEM>>>(u, d);

    dim3 grid(WW/64, HH/8, 4);
    kconvH<128, true><<<grid, 512, CONVH_SMEM>>>(puh, pdh, pbuf0, pbuf1,
                                                 pw1a, pw2a, pt0, pt1);
    kconvH<64, false><<<grid, 512, CONVH_SMEM>>>(pt0, pt1, nullptr, nullptr,
                                                 pw1b, pw2b, out, out + TENSOR_ELEMS);
}

// round 13
// speedup vs baseline: 2.1845x; 1.0845x over previous
#include <cuda_runtime.h>
#include <cuda_fp16.h>
#include <cstddef>
#include <cstdint>

#define HH 320
#define WW 320
#define CC 64
#define BB 2
#define HW (HH*WW)              // 102400
#define CHW ((size_t)CC*HW)     // 6553600
#define TENSOR_ELEMS (BB*CHW)   // 13107200
#define CPHW ((size_t)32*HW)    // pair-planes per batch image

// Scratch (static device arrays; no allocation allowed)
__device__ uint32_t g_Mth[2*CC*32];          // fp16x2 Mt pairs: [dir][b][ap]
__device__ uint32_t g_bufh[2][BB*CPHW];      // attention buffers, fp16 pair-packed
__device__ uint32_t g_th[2][BB*CPHW];        // conv1 outputs, fp16 pair-packed
__device__ uint32_t g_uh[BB*CPHW];           // fp16 pair-packed u (written by kattn)
__device__ uint32_t g_dh[BB*CPHW];           // fp16 pair-packed d
// fp16 conv weights: [chunk][tap9][o64][kp8] half2 words
__device__ uint32_t g_wh1a[8*9*64*8];
__device__ uint32_t g_wh2a[8*9*64*8];
__device__ uint32_t g_wh1b[4*9*64*8];
__device__ uint32_t g_wh2b[4*9*64*8];

__device__ __forceinline__ void mma_f16(float4& d,
        uint32_t a0, uint32_t a1, uint32_t a2, uint32_t a3,
        uint32_t b0, uint32_t b1) {
    asm("mma.sync.aligned.m16n8k16.row.col.f32.f16.f16.f32 "
        "{%0,%1,%2,%3}, {%4,%5,%6,%7}, {%8,%9}, {%0,%1,%2,%3};"
        : "+f"(d.x), "+f"(d.y), "+f"(d.z), "+f"(d.w)
        : "r"(a0), "r"(a1), "r"(a2), "r"(a3), "r"(b0), "r"(b1));
}
__device__ __forceinline__ uint32_t prmt(uint32_t lo, uint32_t hi, uint32_t sel) {
    uint32_t r; asm("prmt.b32 %0, %1, %2, %3;" : "=r"(r) : "r"(lo), "r"(hi), "r"(sel));
    return r;
}
__device__ __forceinline__ void cp16(uint32_t saddr, const void* gaddr, uint32_t sz) {
    asm volatile("cp.async.cg.shared.global [%0], [%1], 16, %2;"
                 :: "r"(saddr), "l"(gaddr), "r"(sz));
}
__device__ __forceinline__ uint32_t h2u(__half2 h) { return *(uint32_t*)&h; }

// ---------------------------------------------------------------------------
// prep: fp16 conv weights (kp perm + sigma rows)
// ---------------------------------------------------------------------------
__device__ __forceinline__ void prepwh_one(const float* __restrict__ W,
                                           uint32_t* __restrict__ dst,
                                           int cin, int i) {
    int w      = i & 7;
    int o_st   = (i >> 3) & 63;
    int t      = (i >> 9) % 9;
    int chunk  = i / (9*64*8);
    int kpc = (w >> 1) + (w & 1)*4;
    int c0  = chunk*16 + 2*kpc;
    int r   = o_st & 15, tb = o_st & 48;
    int oc  = tb + (r & 7)*2 + (r >> 3);
    float w0 = W[((size_t)oc*cin + c0)*9 + t];
    float w1 = W[((size_t)oc*cin + c0 + 1)*9 + t];
    dst[i] = h2u(__floats2half2_rn(w0, w1));
}

#define WHA (8*9*64*8)   // 36864
#define WHB (4*9*64*8)   // 18432

__global__ void kprepwAll(const float* __restrict__ W1a, const float* __restrict__ W2a,
                          const float* __restrict__ W1b, const float* __restrict__ W2b) {
    int total = 2*WHA + 2*WHB;
    for (int i = blockIdx.x*256 + threadIdx.x; i < total; i += gridDim.x*256) {
        if (i < WHA)               prepwh_one(W1a, g_wh1a, 128, i);
        else if (i < 2*WHA)        prepwh_one(W2a, g_wh2a, 128, i - WHA);
        else if (i < 2*WHA + WHB)  prepwh_one(W1b, g_wh1b, 64,  i - 2*WHA);
        else                       prepwh_one(W2b, g_wh2b, 64,  i - 2*WHA - WHB);
    }
}

// ---------------------------------------------------------------------------
// Kernel 1: Mth[dir][b][ap] = half2( log2e*Mt[b][2ap], log2e*Mt[b][2ap+1] )
// ---------------------------------------------------------------------------
__global__ void kcomputeM2(const float* __restrict__ Wu1, const float* __restrict__ Wd2,
                           const float* __restrict__ Wd1, const float* __restrict__ Wu2) {
    __shared__ float sq[64*64];
    __shared__ float sk[64*64];
    int dir = blockIdx.x;
    const float* Wq = dir ? Wd1 : Wu1;
    const float* Wk = dir ? Wu2 : Wd2;
    int t = threadIdx.x;
    for (int i = t; i < 4096; i += 256) { sq[i] = Wq[i]; sk[i] = Wk[i]; }
    __syncthreads();
    const float LOG2E = 1.4426950408889634f;
    for (int i = t; i < 2048; i += 256) {
        int b  = i & 63;
        int ap = i >> 6;
        float s0 = 0.f, s1 = 0.f;
        #pragma unroll 16
        for (int c = 0; c < 64; c++) {
            s0 += sq[c*64 + 2*ap]     * sk[c*64 + b];
            s1 += sq[c*64 + 2*ap + 1] * sk[c*64 + b];
        }
        g_Mth[dir*2048 + b*32 + ap] = h2u(__floats2half2_rn(s0*LOG2E, s1*LOG2E));
    }
}

// ---------------------------------------------------------------------------
// Kernel 2: fp16 attention with register-resident softmax.
// smem (words): sup[32*328], sdp[32*328], sPh[32*172], sRp[32*40],
//               sO[64*40], sPmax[256], sPsum[256]   => 123392 B
// Also writes packed u/d rows to g_uh/g_dh (feeds conv1; replaces kprepin).
// ---------------------------------------------------------------------------
#define SP  328
#define SPH 172
#define SRP 40
#define ATTN_SMEM ((2*32*SP + 32*SPH + 32*SRP + 64*40 + 256 + 256)*4)

__global__ __launch_bounds__(512)
void kattn(const float* __restrict__ u, const float* __restrict__ d) {
    extern __shared__ uint32_t sm[];
    uint32_t* sup = sm;
    uint32_t* sdp = sm + 32*SP;
    uint32_t* sPh = sm + 2*32*SP;
    uint32_t* sRp = sPh + 32*SPH;
    float*    sO  = (float*)(sRp + 32*SRP);
    float*    sPmax = sO + 64*40;
    float*    sPsum = sPmax + 256;

    int tid  = threadIdx.x;
    int lane = tid & 31, warp = tid >> 5;    // 16 warps
    int gid  = lane >> 2, tid4 = lane & 3;
    int b = blockIdx.x / HH, h = blockIdx.x % HH;
    const float* ubase = u + (size_t)b*CHW + (size_t)h*WW;
    const float* dbase = d + (size_t)b*CHW + (size_t)h*WW;

    // stage pair-packed fp16 rows; also persist to global for conv1
    for (int i = tid; i < 32*80; i += 512) {
        int cp = i / 80, vq = (i % 80)*4;
        float4 ue = *(const float4*)(ubase + (size_t)(2*cp)*HW + vq);
        float4 uo = *(const float4*)(ubase + (size_t)(2*cp+1)*HW + vq);
        float4 de = *(const float4*)(dbase + (size_t)(2*cp)*HW + vq);
        float4 do_ = *(const float4*)(dbase + (size_t)(2*cp+1)*HW + vq);
        uint4 wu, wd;
        wu.x = h2u(__floats2half2_rn(ue.x, uo.x));
        wu.y = h2u(__floats2half2_rn(ue.y, uo.y));
        wu.z = h2u(__floats2half2_rn(ue.z, uo.z));
        wu.w = h2u(__floats2half2_rn(ue.w, uo.w));
        wd.x = h2u(__floats2half2_rn(de.x, do_.x));
        wd.y = h2u(__floats2half2_rn(de.y, do_.y));
        wd.z = h2u(__floats2half2_rn(de.z, do_.z));
        wd.w = h2u(__floats2half2_rn(de.w, do_.w));
        *(uint4*)&sup[cp*SP + vq] = wu;
        *(uint4*)&sdp[cp*SP + vq] = wd;
        size_t go = (size_t)b*CPHW + (size_t)cp*HW + (size_t)h*WW + vq;
        *(uint4*)&g_uh[go] = wu;
        *(uint4*)&g_dh[go] = wd;
    }

    for (int dir = 0; dir < 2; dir++) {
        const uint32_t* sQ = dir ? sdp : sup;
        const uint32_t* sV = dir ? sup : sdp;
        uint32_t* outgh = g_bufh[dir] + (size_t)b*CPHW + (size_t)h*WW;

        const uint32_t* Mth = g_Mth + dir*2048;
        int bg = warp & 3, rq = warp >> 2;
        int r = bg*16 + gid;
        uint32_t am[4][4];
        #pragma unroll
        for (int kk = 0; kk < 4; kk++) {
            am[kk][0] = Mth[r*32 + kk*8 + tid4];
            am[kk][1] = Mth[(r+8)*32 + kk*8 + tid4];
            am[kk][2] = Mth[r*32 + kk*8 + tid4 + 4];
            am[kk][3] = Mth[(r+8)*32 + kk*8 + tid4 + 4];
        }

        for (int q0 = 0; q0 < WW; q0 += 32) {
            __syncthreads();

            // ---- R[b][q]: 16b x 8q per warp, K=64 ----
            {
                float4 rc = make_float4(0.f,0.f,0.f,0.f);
                int qc = q0 + rq*8 + gid;
                #pragma unroll
                for (int kk = 0; kk < 4; kk++) {
                    uint32_t b0 = sQ[(kk*8 + tid4)*SP + qc];
                    uint32_t b1 = sQ[(kk*8 + tid4 + 4)*SP + qc];
                    mma_f16(rc, am[kk][0], am[kk][1], am[kk][2], am[kk][3], b0, b1);
                }
                __half* rh = (__half*)sRp;
                int bp  = bg*8 + (gid >> 1);
                int par = gid & 1;
                int qq  = rq*8 + 2*tid4;
                rh[(bp*SRP + qq)*2 + par]         = __float2half_rn(rc.x);
                rh[(bp*SRP + qq + 1)*2 + par]     = __float2half_rn(rc.y);
                rh[((bp+4)*SRP + qq)*2 + par]     = __float2half_rn(rc.z);
                rh[((bp+4)*SRP + qq + 1)*2 + par] = __float2half_rn(rc.w);
            }
            __syncthreads();

            // ---- S[q][v] in registers + register softmax ----
            {
                int qg = warp >> 3, vg = warp & 7;
                float4 sc[5];
                #pragma unroll
                for (int nt = 0; nt < 5; nt++) sc[nt] = make_float4(0.f,0.f,0.f,0.f);
                #pragma unroll
                for (int kk = 0; kk < 4; kk++) {
                    uint32_t a0 = sRp[(kk*8 + tid4)*SRP + qg*16 + gid];
                    uint32_t a1 = sRp[(kk*8 + tid4)*SRP + qg*16 + gid + 8];
                    uint32_t a2 = sRp[(kk*8 + tid4 + 4)*SRP + qg*16 + gid];
                    uint32_t a3 = sRp[(kk*8 + tid4 + 4)*SRP + qg*16 + gid + 8];
                    #pragma unroll
                    for (int nt = 0; nt < 5; nt++) {
                        int vv = vg*40 + nt*8 + gid;
                        uint32_t b0 = sV[(kk*8 + tid4)*SP + vv];
                        uint32_t b1 = sV[(kk*8 + tid4 + 4)*SP + vv];
                        mma_f16(sc[nt], a0, a1, a2, a3, b0, b1);
                    }
                }
                int row0 = qg*16 + gid;
                // partial row max over this warp's 40 v (quad reduce over tid4)
                float m0 = sc[0].x, m1 = sc[0].z;
                #pragma unroll
                for (int nt = 0; nt < 5; nt++) {
                    m0 = fmaxf(m0, fmaxf(sc[nt].x, sc[nt].y));
                    m1 = fmaxf(m1, fmaxf(sc[nt].z, sc[nt].w));
                }
                m0 = fmaxf(m0, __shfl_xor_sync(~0u, m0, 1));
                m0 = fmaxf(m0, __shfl_xor_sync(~0u, m0, 2));
                m1 = fmaxf(m1, __shfl_xor_sync(~0u, m1, 1));
                m1 = fmaxf(m1, __shfl_xor_sync(~0u, m1, 2));
                if (tid4 == 0) {
                    sPmax[row0*8 + vg]      = m0;
                    sPmax[(row0+8)*8 + vg]  = m1;
                }
                __syncthreads();
                // global row max
                float4 ga = *(const float4*)&sPmax[row0*8];
                float4 gb = *(const float4*)&sPmax[row0*8 + 4];
                float gm0 = fmaxf(fmaxf(fmaxf(ga.x, ga.y), fmaxf(ga.z, ga.w)),
                                  fmaxf(fmaxf(gb.x, gb.y), fmaxf(gb.z, gb.w)));
                ga = *(const float4*)&sPmax[(row0+8)*8];
                gb = *(const float4*)&sPmax[(row0+8)*8 + 4];
                float gm1 = fmaxf(fmaxf(fmaxf(ga.x, ga.y), fmaxf(ga.z, ga.w)),
                                  fmaxf(fmaxf(gb.x, gb.y), fmaxf(gb.z, gb.w)));
                // exp + partial sums
                float s0 = 0.f, s1 = 0.f;
                #pragma unroll
                for (int nt = 0; nt < 5; nt++) {
                    sc[nt].x = exp2f(sc[nt].x - gm0);
                    sc[nt].y = exp2f(sc[nt].y - gm0);
                    sc[nt].z = exp2f(sc[nt].z - gm1);
                    sc[nt].w = exp2f(sc[nt].w - gm1);
                    s0 += sc[nt].x + sc[nt].y;
                    s1 += sc[nt].z + sc[nt].w;
                }
                s0 += __shfl_xor_sync(~0u, s0, 1);
                s0 += __shfl_xor_sync(~0u, s0, 2);
                s1 += __shfl_xor_sync(~0u, s1, 1);
                s1 += __shfl_xor_sync(~0u, s1, 2);
                if (tid4 == 0) {
                    sPsum[row0*8 + vg]     = s0;
                    sPsum[(row0+8)*8 + vg] = s1;
                }
                __syncthreads();
                ga = *(const float4*)&sPsum[row0*8];
                gb = *(const float4*)&sPsum[row0*8 + 4];
                float inv0 = 1.f / (ga.x + ga.y + ga.z + ga.w + gb.x + gb.y + gb.z + gb.w);
                ga = *(const float4*)&sPsum[(row0+8)*8];
                gb = *(const float4*)&sPsum[(row0+8)*8 + 4];
                float inv1 = 1.f / (ga.x + ga.y + ga.z + ga.w + gb.x + gb.y + gb.z + gb.w);
                // normalize + pack fp16 P (word index = v/2)
                #pragma unroll
                for (int nt = 0; nt < 5; nt++) {
                    int vp = vg*20 + nt*4 + tid4;
                    sPh[row0*SPH + vp]     = h2u(__floats2half2_rn(sc[nt].x*inv0, sc[nt].y*inv0));
                    sPh[(row0+8)*SPH + vp] = h2u(__floats2half2_rn(sc[nt].z*inv1, sc[nt].w*inv1));
                }
            }
            __syncthreads();

            // ---- attend: warp = cg(4) x aqg(2) x kh(2); rows = adjacent ch pair ----
            {
                int cg = warp & 3, aqg = (warp >> 2) & 1, kh = warp >> 3;
                int gam = cg*8 + gid;          // channel pair index
                int c0  = 2*gam;
                float4 oc[2];
                oc[0] = make_float4(0.f,0.f,0.f,0.f);
                oc[1] = make_float4(0.f,0.f,0.f,0.f);
                #pragma unroll 2
                for (int kk = 0; kk < 10; kk++) {
                    int kb = kh*160 + kk*16;
                    uint2 w0 = *(const uint2*)&sV[gam*SP + kb + 2*tid4];
                    uint2 w1 = *(const uint2*)&sV[gam*SP + kb + 2*tid4 + 8];
                    uint32_t a0 = prmt(w0.x, w0.y, 0x5410u);
                    uint32_t a1 = prmt(w0.x, w0.y, 0x7632u);
                    uint32_t a2 = prmt(w1.x, w1.y, 0x5410u);
                    uint32_t a3 = prmt(w1.x, w1.y, 0x7632u);
                    int vp = (kb >> 1) + tid4;
                    #pragma unroll
                    for (int nt = 0; nt < 2; nt++) {
                        int q = aqg*16 + nt*8 + gid;
                        uint32_t b0 = sPh[q*SPH + vp];
                        uint32_t b1 = sPh[q*SPH + vp + 4];
                        mma_f16(oc[nt], a0, a1, a2, a3, b0, b1);
                    }
                }
                if (kh == 0) {
                    #pragma unroll
                    for (int nt = 0; nt < 2; nt++) {
                        int q = aqg*16 + nt*8 + 2*tid4;
                        *(float2*)&sO[c0*40 + q]     = make_float2(oc[nt].x, oc[nt].y);
                        *(float2*)&sO[(c0+1)*40 + q] = make_float2(oc[nt].z, oc[nt].w);
                    }
                }
                __syncthreads();
                if (kh == 1) {
                    #pragma unroll
                    for (int nt = 0; nt < 2; nt++) {
                        int q = aqg*16 + nt*8 + 2*tid4;
                        float2 r0 = *(const float2*)&sO[c0*40 + q];
                        float2 r1 = *(const float2*)&sO[(c0+1)*40 + q];
                        uint2 wv;
                        wv.x = h2u(__floats2half2_rn(oc[nt].x + r0.x, oc[nt].z + r1.x));
                        wv.y = h2u(__floats2half2_rn(oc[nt].y + r0.y, oc[nt].w + r1.y));
                        *(uint2*)(outgh + (size_t)gam*HW + q0 + q) = wv;
                    }
                }
            }
        }
        __syncthreads();
    }
}

// ---------------------------------------------------------------------------
// Kernel 3: fp16 implicit-GEMM 3x3 conv (unchanged from R12).
// ---------------------------------------------------------------------------
#define PLH 728
#define SINH (8*PLH)                    // 5824
#define SWH  (9*64*8)                   // 4608
#define STH  (SINH + SWH)               // 10432
#define CONVH_SMEM (STH*2*4)            // 83456 bytes

template<int CIN, bool FUSE>
__global__ __launch_bounds__(512, 1)
void kconvH(const uint32_t* __restrict__ in1u, const uint32_t* __restrict__ in1d,
            const uint32_t* __restrict__ in2u, const uint32_t* __restrict__ in2d,
            const uint32_t* __restrict__ wpu,  const uint32_t* __restrict__ wpd,
            void* __restrict__ outu, void* __restrict__ outd) {
    extern __shared__ uint32_t csm[];

    int tid  = threadIdx.x;
    int lane = tid & 31, warp = tid >> 5;
    int x0 = blockIdx.x * 64;
    int y0 = blockIdx.y * 8;
    int z  = blockIdx.z;
    int b  = z & 1, st = z >> 1;

    const uint32_t* in1 = (st ? in1d : in1u) + (size_t)b*CPHW;
    const uint32_t* in2 = (CIN == 128) ? ((st ? in2d : in2u) + (size_t)b*CPHW) : nullptr;
    const uint32_t* wp  = st ? wpd  : wpu;
    void* outv          = st ? outd : outu;

    int warp_o = warp & 1;
    int warp_y = warp >> 1;         // 0..7
    int lq = lane >> 2;
    int lr = lane & 3;

    uint32_t s_base = (uint32_t)__cvta_generic_to_shared(csm);
    const int NCH = CIN/16;

    auto stage = [&](int cb, int bufi) {
        uint32_t sb = s_base + bufi*STH*4;
        for (int i = tid; i < 1440; i += 512) {
            int c   = i / 180;
            int rem = i % 180;
            int r   = rem / 18;
            int q   = rem % 18;
            int gy = y0 + r - 1;
            int gx = x0 - 4 + q*4;
            uint32_t ok = (gy >= 0 && gy < HH && gx >= 0 && gx < WW) ? 16u : 0u;
            int cpg = cb*8 + c;
            const uint32_t* plane = (CIN == 128 && cpg >= 32)
                                  ? in2 + (size_t)(cpg - 32)*HW
                                  : in1 + (size_t)cpg*HW;
            const uint32_t* gsrc = ok ? (plane + gy*WW + gx) : plane;
            cp16(sb + (c*PLH + r*72 + q*4)*4, gsrc, ok);
        }
        const uint32_t* wsrc = wp + cb*SWH;
        for (int i = tid; i < SWH/4; i += 512)
            cp16(sb + (SINH + i*4)*4, wsrc + i*4, 16);
    };

    float4 acc[2][8];
    #pragma unroll
    for (int mt = 0; mt < 2; mt++)
        #pragma unroll
        for (int nt = 0; nt < 8; nt++) acc[mt][nt] = make_float4(0.f,0.f,0.f,0.f);

    stage(0, 0);
    asm volatile("cp.async.commit_group;" ::: "memory");

    for (int cb = 0; cb < NCH; cb++) {
        if (cb + 1 < NCH) {
            stage(cb + 1, (cb + 1) & 1);
            asm volatile("cp.async.commit_group;" ::: "memory");
            asm volatile("cp.async.wait_group 1;" ::: "memory");
        } else {
            asm volatile("cp.async.wait_group 0;" ::: "memory");
        }
        __syncthreads();

        const uint32_t* sin_ = csm + (cb & 1)*STH;
        const uint32_t* sw_  = sin_ + SINH;

        #pragma unroll
        for (int t = 0; t < 9; t++) {
            int ky = t/3, kx = t - ky*3;
            int row = warp_y + ky;
            int bbase = row*72 + kx + 3 + lq;
            uint2 ae0 = *(const uint2*)&sw_[(t*64 + warp_o*32 + lq)*8 + 2*lr];
            uint2 ao0 = *(const uint2*)&sw_[(t*64 + warp_o*32 + lq + 8)*8 + 2*lr];
            uint2 ae1 = *(const uint2*)&sw_[(t*64 + warp_o*32 + 16 + lq)*8 + 2*lr];
            uint2 ao1 = *(const uint2*)&sw_[(t*64 + warp_o*32 + 16 + lq + 8)*8 + 2*lr];
            int p0 = lr*PLH + bbase;
            int p1 = p0 + 4*PLH;
            #pragma unroll
            for (int nt = 0; nt < 8; nt++) {
                uint32_t b0 = sin_[p0 + 8*nt];
                uint32_t b1 = sin_[p1 + 8*nt];
                mma_f16(acc[0][nt], ae0.x, ao0.x, ae0.y, ao0.y, b0, b1);
                mma_f16(acc[1][nt], ae1.x, ao1.x, ae1.y, ao1.y, b0, b1);
            }
        }
        __syncthreads();
    }

    int y = y0 + warp_y;
    #pragma unroll
    for (int mt = 0; mt < 2; mt++) {
        int tb  = warp_o*32 + mt*16;
        int ch0 = tb + 2*lq;
        int cp  = (tb >> 1) + lq;
        #pragma unroll
        for (int nt = 0; nt < 8; nt++) {
            int x = x0 + nt*8 + 2*lr;
            float4 v = acc[mt][nt];
            if (FUSE) {
                uint32_t* outp = (uint32_t*)outv;
                uint2 wv;
                wv.x = h2u(__floats2half2_rn(fmaxf(v.x, 0.f), fmaxf(v.z, 0.f)));
                wv.y = h2u(__floats2half2_rn(fmaxf(v.y, 0.f), fmaxf(v.w, 0.f)));
                *(uint2*)(outp + (size_t)b*CPHW + (size_t)cp*HW + (size_t)y*WW + x) = wv;
            } else {
                float* outp = (float*)outv;
                size_t off = (size_t)b*CHW + (size_t)ch0*HW + (size_t)y*WW + x;
                *(float2*)(outp + off)      = make_float2(v.x, v.y);
                *(float2*)(outp + off + HW) = make_float2(v.z, v.w);
            }
        }
    }
}

// ---------------------------------------------------------------------------
extern "C" void kernel_launch(void* const* d_in, const int* in_sizes, int n_in,
                              void* d_out, int out_size) {
    const float* u   = (const float*)d_in[0];
    const float* d   = (const float*)d_in[1];
    const float* Wu1 = (const float*)d_in[2];
    const float* Wu2 = (const float*)d_in[3];
    const float* Wd1 = (const float*)d_in[4];
    const float* Wd2 = (const float*)d_in[5];
    const float* W1a = (const float*)d_in[6];
    const float* W1b = (const float*)d_in[7];
    const float* W2a = (const float*)d_in[8];
    const float* W2b = (const float*)d_in[9];
    float* out = (float*)d_out;

    cudaFuncSetAttribute(kattn, cudaFuncAttributeMaxDynamicSharedMemorySize, ATTN_SMEM);
    cudaFuncSetAttribute(kconvH<128, true>,  cudaFuncAttributeMaxDynamicSharedMemorySize, CONVH_SMEM);
    cudaFuncSetAttribute(kconvH<64, false>,  cudaFuncAttributeMaxDynamicSharedMemorySize, CONVH_SMEM);

    uint32_t *pbuf0, *pbuf1, *pt0, *pt1, *puh, *pdh;
    uint32_t *pw1a, *pw2a, *pw1b, *pw2b;
    cudaGetSymbolAddress((void**)&pbuf0, g_bufh);  pbuf1 = pbuf0 + BB*CPHW;
    cudaGetSymbolAddress((void**)&pt0,   g_th);    pt1   = pt0   + BB*CPHW;
    cudaGetSymbolAddress((void**)&puh,   g_uh);
    cudaGetSymbolAddress((void**)&pdh,   g_dh);
    cudaGetSymbolAddress((void**)&pw1a,  g_wh1a);
    cudaGetSymbolAddress((void**)&pw2a,  g_wh2a);
    cudaGetSymbolAddress((void**)&pw1b,  g_wh1b);
    cudaGetSymbolAddress((void**)&pw2b,  g_wh2b);

    kprepwAll<<<432, 256>>>(W1a, W2a, W1b, W2b);
    kcomputeM2<<<2, 256>>>(Wu1, Wd2, Wd1, Wu2);

    kattn<<<BB*HH, 512, ATTN_SMEM>>>(u, d);

    dim3 grid(WW/64, HH/8, 4);
    kconvH<128, true><<<grid, 512, CONVH_SMEM>>>(puh, pdh, pbuf0, pbuf1,
                                                 pw1a, pw2a, pt0, pt1);
    kconvH<64, false><<<grid, 512, CONVH_SMEM>>>(pt0, pt1, nullptr, nullptr,
                                                 pw1b, pw2b, out, out + TENSOR_ELEMS);
}

// round 14
// speedup vs baseline: 2.2872x; 1.0470x over previous
#include <cuda_runtime.h>
#include <cuda_fp16.h>
#include <cstddef>
#include <cstdint>

#define HH 320
#define WW 320
#define CC 64
#define BB 2
#define HW (HH*WW)              // 102400
#define CHW ((size_t)CC*HW)     // 6553600
#define TENSOR_ELEMS (BB*CHW)   // 13107200
#define CPHW ((size_t)32*HW)    // pair-planes per batch image

// Scratch (static device arrays; no allocation allowed)
__device__ uint32_t g_Mth[2*CC*32];          // fp16x2 Mt pairs: [dir][b][ap]
__device__ uint32_t g_bufh[2][BB*CPHW];      // attention buffers, fp16 pair-packed
__device__ uint32_t g_th[2][BB*CPHW];        // conv1 outputs, fp16 pair-packed
__device__ uint32_t g_uh[BB*CPHW];           // fp16 pair-packed u (written by kattn)
__device__ uint32_t g_dh[BB*CPHW];           // fp16 pair-packed d
// fp16 conv weights: [chunk][tap9][o64][kp8] half2 words
__device__ uint32_t g_wh1a[8*9*64*8];
__device__ uint32_t g_wh2a[8*9*64*8];
__device__ uint32_t g_wh1b[4*9*64*8];
__device__ uint32_t g_wh2b[4*9*64*8];

__device__ __forceinline__ void mma_f16(float4& d,
        uint32_t a0, uint32_t a1, uint32_t a2, uint32_t a3,
        uint32_t b0, uint32_t b1) {
    asm("mma.sync.aligned.m16n8k16.row.col.f32.f16.f16.f32 "
        "{%0,%1,%2,%3}, {%4,%5,%6,%7}, {%8,%9}, {%0,%1,%2,%3};"
        : "+f"(d.x), "+f"(d.y), "+f"(d.z), "+f"(d.w)
        : "r"(a0), "r"(a1), "r"(a2), "r"(a3), "r"(b0), "r"(b1));
}
__device__ __forceinline__ uint32_t prmt(uint32_t lo, uint32_t hi, uint32_t sel) {
    uint32_t r; asm("prmt.b32 %0, %1, %2, %3;" : "=r"(r) : "r"(lo), "r"(hi), "r"(sel));
    return r;
}
__device__ __forceinline__ void cp16(uint32_t saddr, const void* gaddr, uint32_t sz) {
    asm volatile("cp.async.cg.shared.global [%0], [%1], 16, %2;"
                 :: "r"(saddr), "l"(gaddr), "r"(sz));
}
__device__ __forceinline__ uint32_t h2u(__half2 h) { return *(uint32_t*)&h; }

// ---------------------------------------------------------------------------
// prep: fp16 conv weights (kp perm + sigma rows)
// ---------------------------------------------------------------------------
__device__ __forceinline__ void prepwh_one(const float* __restrict__ W,
                                           uint32_t* __restrict__ dst,
                                           int cin, int i) {
    int w      = i & 7;
    int o_st   = (i >> 3) & 63;
    int t      = (i >> 9) % 9;
    int chunk  = i / (9*64*8);
    int kpc = (w >> 1) + (w & 1)*4;
    int c0  = chunk*16 + 2*kpc;
    int r   = o_st & 15, tb = o_st & 48;
    int oc  = tb + (r & 7)*2 + (r >> 3);
    float w0 = W[((size_t)oc*cin + c0)*9 + t];
    float w1 = W[((size_t)oc*cin + c0 + 1)*9 + t];
    dst[i] = h2u(__floats2half2_rn(w0, w1));
}

#define WHA (8*9*64*8)   // 36864
#define WHB (4*9*64*8)   // 18432

__global__ void kprepwAll(const float* __restrict__ W1a, const float* __restrict__ W2a,
                          const float* __restrict__ W1b, const float* __restrict__ W2b) {
    int total = 2*WHA + 2*WHB;
    for (int i = blockIdx.x*256 + threadIdx.x; i < total; i += gridDim.x*256) {
        if (i < WHA)               prepwh_one(W1a, g_wh1a, 128, i);
        else if (i < 2*WHA)        prepwh_one(W2a, g_wh2a, 128, i - WHA);
        else if (i < 2*WHA + WHB)  prepwh_one(W1b, g_wh1b, 64,  i - 2*WHA);
        else                       prepwh_one(W2b, g_wh2b, 64,  i - 2*WHA - WHB);
    }
}

// ---------------------------------------------------------------------------
// Kernel 1: Mth[dir][b][ap] = half2( log2e*Mt[b][2ap], log2e*Mt[b][2ap+1] )
// ---------------------------------------------------------------------------
__global__ void kcomputeM2(const float* __restrict__ Wu1, const float* __restrict__ Wd2,
                           const float* __restrict__ Wd1, const float* __restrict__ Wu2) {
    __shared__ float sq[64*64];
    __shared__ float sk[64*64];
    int dir = blockIdx.x;
    const float* Wq = dir ? Wd1 : Wu1;
    const float* Wk = dir ? Wu2 : Wd2;
    int t = threadIdx.x;
    for (int i = t; i < 4096; i += 256) { sq[i] = Wq[i]; sk[i] = Wk[i]; }
    __syncthreads();
    const float LOG2E = 1.4426950408889634f;
    for (int i = t; i < 2048; i += 256) {
        int b  = i & 63;
        int ap = i >> 6;
        float s0 = 0.f, s1 = 0.f;
        #pragma unroll 16
        for (int c = 0; c < 64; c++) {
            s0 += sq[c*64 + 2*ap]     * sk[c*64 + b];
            s1 += sq[c*64 + 2*ap + 1] * sk[c*64 + b];
        }
        g_Mth[dir*2048 + b*32 + ap] = h2u(__floats2half2_rn(s0*LOG2E, s1*LOG2E));
    }
}

// ---------------------------------------------------------------------------
// Kernel 2: fp16 attention, register softmax WITHOUT max pass (scores bounded).
// smem (words): sup[32*328], sdp[32*328], sPh[32*172], sRp[32*40],
//               sO[64*40], sPsum[256]
// ---------------------------------------------------------------------------
#define SP  328
#define SPH 172
#define SRP 40
#define ATTN_SMEM ((2*32*SP + 32*SPH + 32*SRP + 64*40 + 256)*4)

__global__ __launch_bounds__(512)
void kattn(const float* __restrict__ u, const float* __restrict__ d) {
    extern __shared__ uint32_t sm[];
    uint32_t* sup = sm;
    uint32_t* sdp = sm + 32*SP;
    uint32_t* sPh = sm + 2*32*SP;
    uint32_t* sRp = sPh + 32*SPH;
    float*    sO  = (float*)(sRp + 32*SRP);
    float*    sPsum = sO + 64*40;

    int tid  = threadIdx.x;
    int lane = tid & 31, warp = tid >> 5;    // 16 warps
    int gid  = lane >> 2, tid4 = lane & 3;
    int b = blockIdx.x / HH, h = blockIdx.x % HH;
    const float* ubase = u + (size_t)b*CHW + (size_t)h*WW;
    const float* dbase = d + (size_t)b*CHW + (size_t)h*WW;

    // stage pair-packed fp16 rows; also persist to global for conv1
    for (int i = tid; i < 32*80; i += 512) {
        int cp = i / 80, vq = (i % 80)*4;
        float4 ue = *(const float4*)(ubase + (size_t)(2*cp)*HW + vq);
        float4 uo = *(const float4*)(ubase + (size_t)(2*cp+1)*HW + vq);
        float4 de = *(const float4*)(dbase + (size_t)(2*cp)*HW + vq);
        float4 do_ = *(const float4*)(dbase + (size_t)(2*cp+1)*HW + vq);
        uint4 wu, wd;
        wu.x = h2u(__floats2half2_rn(ue.x, uo.x));
        wu.y = h2u(__floats2half2_rn(ue.y, uo.y));
        wu.z = h2u(__floats2half2_rn(ue.z, uo.z));
        wu.w = h2u(__floats2half2_rn(ue.w, uo.w));
        wd.x = h2u(__floats2half2_rn(de.x, do_.x));
        wd.y = h2u(__floats2half2_rn(de.y, do_.y));
        wd.z = h2u(__floats2half2_rn(de.z, do_.z));
        wd.w = h2u(__floats2half2_rn(de.w, do_.w));
        *(uint4*)&sup[cp*SP + vq] = wu;
        *(uint4*)&sdp[cp*SP + vq] = wd;
        size_t go = (size_t)b*CPHW + (size_t)cp*HW + (size_t)h*WW + vq;
        *(uint4*)&g_uh[go] = wu;
        *(uint4*)&g_dh[go] = wd;
    }

    for (int dir = 0; dir < 2; dir++) {
        const uint32_t* sQ = dir ? sdp : sup;
        const uint32_t* sV = dir ? sup : sdp;
        uint32_t* outgh = g_bufh[dir] + (size_t)b*CPHW + (size_t)h*WW;

        const uint32_t* Mth = g_Mth + dir*2048;
        int bg = warp & 3, rq = warp >> 2;
        int r = bg*16 + gid;
        uint32_t am[4][4];
        #pragma unroll
        for (int kk = 0; kk < 4; kk++) {
            am[kk][0] = Mth[r*32 + kk*8 + tid4];
            am[kk][1] = Mth[(r+8)*32 + kk*8 + tid4];
            am[kk][2] = Mth[r*32 + kk*8 + tid4 + 4];
            am[kk][3] = Mth[(r+8)*32 + kk*8 + tid4 + 4];
        }

        for (int q0 = 0; q0 < WW; q0 += 32) {
            __syncthreads();

            // ---- R[b][q]: 16b x 8q per warp, K=64 ----
            {
                float4 rc = make_float4(0.f,0.f,0.f,0.f);
                int qc = q0 + rq*8 + gid;
                #pragma unroll
                for (int kk = 0; kk < 4; kk++) {
                    uint32_t b0 = sQ[(kk*8 + tid4)*SP + qc];
                    uint32_t b1 = sQ[(kk*8 + tid4 + 4)*SP + qc];
                    mma_f16(rc, am[kk][0], am[kk][1], am[kk][2], am[kk][3], b0, b1);
                }
                __half* rh = (__half*)sRp;
                int bp  = bg*8 + (gid >> 1);
                int par = gid & 1;
                int qq  = rq*8 + 2*tid4;
                rh[(bp*SRP + qq)*2 + par]         = __float2half_rn(rc.x);
                rh[(bp*SRP + qq + 1)*2 + par]     = __float2half_rn(rc.y);
                rh[((bp+4)*SRP + qq)*2 + par]     = __float2half_rn(rc.z);
                rh[((bp+4)*SRP + qq + 1)*2 + par] = __float2half_rn(rc.w);
            }
            __syncthreads();

            // ---- S[q][v] in registers + register softmax (no max pass) ----
            {
                int qg = warp >> 3, vg = warp & 7;
                float4 sc[5];
                #pragma unroll
                for (int nt = 0; nt < 5; nt++) sc[nt] = make_float4(0.f,0.f,0.f,0.f);
                #pragma unroll
                for (int kk = 0; kk < 4; kk++) {
                    uint32_t a0 = sRp[(kk*8 + tid4)*SRP + qg*16 + gid];
                    uint32_t a1 = sRp[(kk*8 + tid4)*SRP + qg*16 + gid + 8];
                    uint32_t a2 = sRp[(kk*8 + tid4 + 4)*SRP + qg*16 + gid];
                    uint32_t a3 = sRp[(kk*8 + tid4 + 4)*SRP + qg*16 + gid + 8];
                    #pragma unroll
                    for (int nt = 0; nt < 5; nt++) {
                        int vv = vg*40 + nt*8 + gid;
                        uint32_t b0 = sV[(kk*8 + tid4)*SP + vv];
                        uint32_t b1 = sV[(kk*8 + tid4 + 4)*SP + vv];
                        mma_f16(sc[nt], a0, a1, a2, a3, b0, b1);
                    }
                }
                int row0 = qg*16 + gid;
                // exp2 directly (scores bounded, |S*log2e| ~ O(1)) + partial sums
                float s0 = 0.f, s1 = 0.f;
                #pragma unroll
                for (int nt = 0; nt < 5; nt++) {
                    sc[nt].x = exp2f(sc[nt].x);
                    sc[nt].y = exp2f(sc[nt].y);
                    sc[nt].z = exp2f(sc[nt].z);
                    sc[nt].w = exp2f(sc[nt].w);
                    s0 += sc[nt].x + sc[nt].y;
                    s1 += sc[nt].z + sc[nt].w;
                }
                s0 += __shfl_xor_sync(~0u, s0, 1);
                s0 += __shfl_xor_sync(~0u, s0, 2);
                s1 += __shfl_xor_sync(~0u, s1, 1);
                s1 += __shfl_xor_sync(~0u, s1, 2);
                if (tid4 == 0) {
                    sPsum[row0*8 + vg]     = s0;
                    sPsum[(row0+8)*8 + vg] = s1;
                }
                __syncthreads();
                float4 ga = *(const float4*)&sPsum[row0*8];
                float4 gb = *(const float4*)&sPsum[row0*8 + 4];
                float inv0 = 1.f / (ga.x + ga.y + ga.z + ga.w + gb.x + gb.y + gb.z + gb.w);
                ga = *(const float4*)&sPsum[(row0+8)*8];
                gb = *(const float4*)&sPsum[(row0+8)*8 + 4];
                float inv1 = 1.f / (ga.x + ga.y + ga.z + ga.w + gb.x + gb.y + gb.z + gb.w);
                // normalize + pack fp16 P (word index = v/2)
                #pragma unroll
                for (int nt = 0; nt < 5; nt++) {
                    int vp = vg*20 + nt*4 + tid4;
                    sPh[row0*SPH + vp]     = h2u(__floats2half2_rn(sc[nt].x*inv0, sc[nt].y*inv0));
                    sPh[(row0+8)*SPH + vp] = h2u(__floats2half2_rn(sc[nt].z*inv1, sc[nt].w*inv1));
                }
            }
            __syncthreads();

            // ---- attend: warp = cg(4) x aqg(2) x kh(2); rows = adjacent ch pair ----
            {
                int cg = warp & 3, aqg = (warp >> 2) & 1, kh = warp >> 3;
                int gam = cg*8 + gid;          // channel pair index
                int c0  = 2*gam;
                float4 oc[2];
                oc[0] = make_float4(0.f,0.f,0.f,0.f);
                oc[1] = make_float4(0.f,0.f,0.f,0.f);
                #pragma unroll 2
                for (int kk = 0; kk < 10; kk++) {
                    int kb = kh*160 + kk*16;
                    uint2 w0 = *(const uint2*)&sV[gam*SP + kb + 2*tid4];
                    uint2 w1 = *(const uint2*)&sV[gam*SP + kb + 2*tid4 + 8];
                    uint32_t a0 = prmt(w0.x, w0.y, 0x5410u);
                    uint32_t a1 = prmt(w0.x, w0.y, 0x7632u);
                    uint32_t a2 = prmt(w1.x, w1.y, 0x5410u);
                    uint32_t a3 = prmt(w1.x, w1.y, 0x7632u);
                    int vp = (kb >> 1) + tid4;
                    #pragma unroll
                    for (int nt = 0; nt < 2; nt++) {
                        int q = aqg*16 + nt*8 + gid;
                        uint32_t b0 = sPh[q*SPH + vp];
                        uint32_t b1 = sPh[q*SPH + vp + 4];
                        mma_f16(oc[nt], a0, a1, a2, a3, b0, b1);
                    }
                }
                if (kh == 0) {
                    #pragma unroll
                    for (int nt = 0; nt < 2; nt++) {
                        int q = aqg*16 + nt*8 + 2*tid4;
                        *(float2*)&sO[c0*40 + q]     = make_float2(oc[nt].x, oc[nt].y);
                        *(float2*)&sO[(c0+1)*40 + q] = make_float2(oc[nt].z, oc[nt].w);
                    }
                }
                __syncthreads();
                if (kh == 1) {
                    #pragma unroll
                    for (int nt = 0; nt < 2; nt++) {
                        int q = aqg*16 + nt*8 + 2*tid4;
                        float2 r0 = *(const float2*)&sO[c0*40 + q];
                        float2 r1 = *(const float2*)&sO[(c0+1)*40 + q];
                        uint2 wv;
                        wv.x = h2u(__floats2half2_rn(oc[nt].x + r0.x, oc[nt].z + r1.x));
                        wv.y = h2u(__floats2half2_rn(oc[nt].y + r0.y, oc[nt].w + r1.y));
                        *(uint2*)(outgh + (size_t)gam*HW + q0 + q) = wv;
                    }
                }
            }
        }
        __syncthreads();
    }
}

// ---------------------------------------------------------------------------
// Kernel 3: fp16 implicit-GEMM 3x3 conv; staging indices hoisted out of the
// chunk loop (chunk-invariant decomposition precomputed per thread).
// ---------------------------------------------------------------------------
#define PLH 728
#define SINH (8*PLH)                    // 5824
#define SWH  (9*64*8)                   // 4608
#define STH  (SINH + SWH)               // 10432
#define CONVH_SMEM (STH*2*4)            // 83456 bytes

template<int CIN, bool FUSE>
__global__ __launch_bounds__(512, 1)
void kconvH(const uint32_t* __restrict__ in1u, const uint32_t* __restrict__ in1d,
            const uint32_t* __restrict__ in2u, const uint32_t* __restrict__ in2d,
            const uint32_t* __restrict__ wpu,  const uint32_t* __restrict__ wpd,
            void* __restrict__ outu, void* __restrict__ outd) {
    extern __shared__ uint32_t csm[];

    int tid  = threadIdx.x;
    int lane = tid & 31, warp = tid >> 5;
    int x0 = blockIdx.x * 64;
    int y0 = blockIdx.y * 8;
    int z  = blockIdx.z;
    int b  = z & 1, st = z >> 1;

    const uint32_t* in1 = (st ? in1d : in1u) + (size_t)b*CPHW;
    const uint32_t* in2 = (CIN == 128) ? ((st ? in2d : in2u) + (size_t)b*CPHW) : nullptr;
    const uint32_t* wp  = st ? wpd  : wpu;
    void* outv          = st ? outd : outu;

    int warp_o = warp & 1;
    int warp_y = warp >> 1;         // 0..7
    int lq = lane >> 2;
    int lr = lane & 3;

    uint32_t s_base = (uint32_t)__cvta_generic_to_shared(csm);
    const int NCH = CIN/16;

    // ---- precompute chunk-invariant staging decomposition ----
    bool has3 = tid < 416;          // 1440 = 2*512 + 416
    int      pc_c[3];
    uint32_t pc_soff[3];
    int      pc_roff[3];
    uint32_t pc_ok[3];
    #pragma unroll
    for (int j = 0; j < 3; j++) {
        int i = tid + j*512;
        if (i < 1440) {
            int c   = i / 180;
            int rem = i % 180;
            int rr  = rem / 18;
            int q   = rem % 18;
            int gy = y0 + rr - 1;
            int gx = x0 - 4 + q*4;
            uint32_t ok = (gy >= 0 && gy < HH && gx >= 0 && gx < WW) ? 16u : 0u;
            pc_c[j]    = c;
            pc_soff[j] = (uint32_t)(c*PLH + rr*72 + q*4)*4;
            pc_roff[j] = ok ? gy*WW + gx : 0;
            pc_ok[j]   = ok;
        } else {
            pc_c[j] = 0; pc_soff[j] = 0; pc_roff[j] = 0; pc_ok[j] = 0;
        }
    }

    auto stage = [&](int cb, int bufi) {
        uint32_t sb = s_base + bufi*STH*4;
        #pragma unroll
        for (int j = 0; j < 3; j++) {
            if (j == 2 && !has3) break;
            int cpg = cb*8 + pc_c[j];
            const uint32_t* plane = (CIN == 128 && cpg >= 32)
                                  ? in2 + (size_t)(cpg - 32)*HW
                                  : in1 + (size_t)cpg*HW;
            cp16(sb + pc_soff[j], plane + pc_roff[j], pc_ok[j]);
        }
        const uint32_t* wsrc = wp + cb*SWH;
        #pragma unroll
        for (int j = 0; j < 3; j++) {
            int i = tid + j*512;
            if (i < SWH/4)
                cp16(sb + (SINH + i*4)*4, wsrc + i*4, 16);
        }
    };

    float4 acc[2][8];
    #pragma unroll
    for (int mt = 0; mt < 2; mt++)
        #pragma unroll
        for (int nt = 0; nt < 8; nt++) acc[mt][nt] = make_float4(0.f,0.f,0.f,0.f);

    stage(0, 0);
    asm volatile("cp.async.commit_group;" ::: "memory");

    for (int cb = 0; cb < NCH; cb++) {
        if (cb + 1 < NCH) {
            stage(cb + 1, (cb + 1) & 1);
            asm volatile("cp.async.commit_group;" ::: "memory");
            asm volatile("cp.async.wait_group 1;" ::: "memory");
        } else {
            asm volatile("cp.async.wait_group 0;" ::: "memory");
        }
        __syncthreads();

        const uint32_t* sin_ = csm + (cb & 1)*STH;
        const uint32_t* sw_  = sin_ + SINH;

        #pragma unroll
        for (int t = 0; t < 9; t++) {
            int ky = t/3, kx = t - ky*3;
            int row = warp_y + ky;
            int bbase = row*72 + kx + 3 + lq;
            uint2 ae0 = *(const uint2*)&sw_[(t*64 + warp_o*32 + lq)*8 + 2*lr];
            uint2 ao0 = *(const uint2*)&sw_[(t*64 + warp_o*32 + lq + 8)*8 + 2*lr];
            uint2 ae1 = *(const uint2*)&sw_[(t*64 + warp_o*32 + 16 + lq)*8 + 2*lr];
            uint2 ao1 = *(const uint2*)&sw_[(t*64 + warp_o*32 + 16 + lq + 8)*8 + 2*lr];
            int p0 = lr*PLH + bbase;
            int p1 = p0 + 4*PLH;
            #pragma unroll
            for (int nt = 0; nt < 8; nt++) {
                uint32_t b0 = sin_[p0 + 8*nt];
                uint32_t b1 = sin_[p1 + 8*nt];
                mma_f16(acc[0][nt], ae0.x, ao0.x, ae0.y, ao0.y, b0, b1);
                mma_f16(acc[1][nt], ae1.x, ao1.x, ae1.y, ao1.y, b0, b1);
            }
        }
        __syncthreads();
    }

    int y = y0 + warp_y;
    #pragma unroll
    for (int mt = 0; mt < 2; mt++) {
        int tb  = warp_o*32 + mt*16;
        int ch0 = tb + 2*lq;
        int cp  = (tb >> 1) + lq;
        #pragma unroll
        for (int nt = 0; nt < 8; nt++) {
            int x = x0 + nt*8 + 2*lr;
            float4 v = acc[mt][nt];
            if (FUSE) {
                uint32_t* outp = (uint32_t*)outv;
                uint2 wv;
                wv.x = h2u(__floats2half2_rn(fmaxf(v.x, 0.f), fmaxf(v.z, 0.f)));
                wv.y = h2u(__floats2half2_rn(fmaxf(v.y, 0.f), fmaxf(v.w, 0.f)));
                *(uint2*)(outp + (size_t)b*CPHW + (size_t)cp*HW + (size_t)y*WW + x) = wv;
            } else {
                float* outp = (float*)outv;
                size_t off = (size_t)b*CHW + (size_t)ch0*HW + (size_t)y*WW + x;
                *(float2*)(outp + off)      = make_float2(v.x, v.y);
                *(float2*)(outp + off + HW) = make_float2(v.z, v.w);
            }
        }
    }
}

// ---------------------------------------------------------------------------
extern "C" void kernel_launch(void* const* d_in, const int* in_sizes, int n_in,
                              void* d_out, int out_size) {
    const float* u   = (const float*)d_in[0];
    const float* d   = (const float*)d_in[1];
    const float* Wu1 = (const float*)d_in[2];
    const float* Wu2 = (const float*)d_in[3];
    const float* Wd1 = (const float*)d_in[4];
    const float* Wd2 = (const float*)d_in[5];
    const float* W1a = (const float*)d_in[6];
    const float* W1b = (const float*)d_in[7];
    const float* W2a = (const float*)d_in[8];
    const float* W2b = (const float*)d_in[9];
    float* out = (float*)d_out;

    cudaFuncSetAttribute(kattn, cudaFuncAttributeMaxDynamicSharedMemorySize, ATTN_SMEM);
    cudaFuncSetAttribute(kconvH<128, true>,  cudaFuncAttributeMaxDynamicSharedMemorySize, CONVH_SMEM);
    cudaFuncSetAttribute(kconvH<64, false>,  cudaFuncAttributeMaxDynamicSharedMemorySize, CONVH_SMEM);

    uint32_t *pbuf0, *pbuf1, *pt0, *pt1, *puh, *pdh;
    uint32_t *pw1a, *pw2a, *pw1b, *pw2b;
    cudaGetSymbolAddress((void**)&pbuf0, g_bufh);  pbuf1 = pbuf0 + BB*CPHW;
    cudaGetSymbolAddress((void**)&pt0,   g_th);    pt1   = pt0   + BB*CPHW;
    cudaGetSymbolAddress((void**)&puh,   g_uh);
    cudaGetSymbolAddress((void**)&pdh,   g_dh);
    cudaGetSymbolAddress((void**)&pw1a,  g_wh1a);
    cudaGetSymbolAddress((void**)&pw2a,  g_wh2a);
    cudaGetSymbolAddress((void**)&pw1b,  g_wh1b);
    cudaGetSymbolAddress((void**)&pw2b,  g_wh2b);

    kprepwAll<<<432, 256>>>(W1a, W2a, W1b, W2b);
    kcomputeM2<<<2, 256>>>(Wu1, Wd2, Wd1, Wu2);

    kattn<<<BB*HH, 512, ATTN_SMEM>>>(u, d);

    dim3 grid(WW/64, HH/8, 4);
    kconvH<128, true><<<grid, 512, CONVH_SMEM>>>(puh, pdh, pbuf0, pbuf1,
                                                 pw1a, pw2a, pt0, pt1);
    kconvH<64, false><<<grid, 512, CONVH_SMEM>>>(pt0, pt1, nullptr, nullptr,
                                                 pw1b, pw2b, out, out + TENSOR_ELEMS);
}